// round 4
// baseline (speedup 1.0000x reference)
#include <cuda_runtime.h>
#include <cuda_bf16.h>
#include <cstdint>
#include <cstddef>

#define Bb 8
#define Cc 768
#define Nn 4096
#define NHh 12
#define HSs 64
#define BCN (Bb*Cc*Nn)   // 25165824

// ---------------- scratch (static device globals; no runtime allocation) ----------
__device__ float g_xx [BCN];
__device__ float g_xxx[BCN];
__device__ float g_t  [Bb*320*Nn];
__device__ float g_x5 [5u*(size_t)BCN];   // slice s: 0=xw 1=xk 2=xv 3=xr 4=xg
__device__ float g_r  [BCN];
__device__ float g_k  [BCN];
__device__ float g_v  [BCN];
__device__ float g_gate[BCN];
__device__ float g_h  [Bb*64*Nn];
__device__ float g_dec[BCN];
__device__ float4 g_rkdv[(size_t)Bb*NHh*Nn*HSs];  // ((b*12+h)*N + n)*64 + j -> (r,k,dec,v)
__device__ float g_y  [BCN];          // (B, N, C)
__device__ float g_y2 [BCN];          // (B, C, N)
__device__ float g_rms[Bb*Nn];
// transposed weights (K, M) layouts
__device__ float g_wt_maaw1[768*320];
__device__ float g_wt_td1  [768*64];
__device__ float g_wt_td2  [64*768];
__device__ float g_wt_r[2*384*384];
__device__ float g_wt_k[2*384*384];
__device__ float g_wt_v[2*384*384];
__device__ float g_wt_g[2*384*384];
__device__ float g_wt_o[2*384*384];

// ---------------- K0: W transpose (M,K)->(K,M), batched over z -------------------
__global__ void wtrans_kernel(const float* __restrict__ W, float* __restrict__ Wt,
                              int M, int K) {
    int z = blockIdx.z;
    const float* Wz = W + (size_t)z * M * K;
    float* Wtz = Wt + (size_t)z * M * K;
    __shared__ float tile[32][33];
    int m0 = blockIdx.y * 32, k0 = blockIdx.x * 32;
    int tx = threadIdx.x, ty = threadIdx.y;
    for (int r = ty; r < 32; r += 8) {
        int m = m0 + r, k = k0 + tx;
        tile[r][tx] = (m < M && k < K) ? Wz[(size_t)m * K + k] : 0.f;
    }
    __syncthreads();
    for (int r = ty; r < 32; r += 8) {
        int k = k0 + r, m = m0 + tx;
        if (k < K && m < M) Wtz[(size_t)k * M + m] = tile[tx][r];
    }
}

// ---------------- K1: q_shift + xx + xxx -------------------------------------------
__global__ void shift_kernel(const float* __restrict__ x, const float* __restrict__ maa_x) {
    size_t idx = (size_t)blockIdx.x * 256 + threadIdx.x;
    if (idx >= (size_t)BCN) return;
    int n = (int)(idx & (Nn - 1));
    int c = (int)((idx >> 12) % Cc);
    int w = n & 63, hh = n >> 6;
    float xv = x[idx], s;
    int mode = c / 192;
    if (mode == 0)      s = (w  > 0 ) ? x[idx - 1 ] : 0.f;
    else if (mode == 1) s = (w  < 63) ? x[idx + 1 ] : 0.f;
    else if (mode == 2) s = (hh > 0 ) ? x[idx - 64] : 0.f;
    else                s = (hh < 63) ? x[idx + 64] : 0.f;
    float d = s - xv;
    g_xx[idx]  = d;
    g_xxx[idx] = fmaf(d, maa_x[c], xv);
}

// ---------------- generic GEMM: Y[z] = act(Wt[z%wmod]^T-view @ X[z]) ---------------
// Wt is (K, M) row-major. X slice: z*K*Nn (K, Nn). Y slice: z*M*Nn (M, Nn).
// ACT: 0 none, 1 tanh, 2 silu, 3 decay: exp(-exp(extra[m] + v))
template<int ACT>
__device__ __forceinline__ float act_fn(float v, float e) {
    if (ACT == 1) return tanhf(v);
    if (ACT == 2) return v / (1.f + expf(-v));
    if (ACT == 3) return expf(-expf(e + v));
    return v;
}

template<int ACT>
__global__ void __launch_bounds__(256) gemm_k(
    const float* __restrict__ Wt, const float* __restrict__ X,
    float* __restrict__ Y, int M, int K, int wmod,
    const float* __restrict__ extra)
{
    const int z  = blockIdx.z;
    const int m0 = blockIdx.y * 64;
    const int n0 = blockIdx.x * 64;
    const float* Wz = Wt + (size_t)(z % wmod) * M * K;
    const float* Xz = X  + (size_t)z * K * Nn;
    float*       Yz = Y  + (size_t)z * M * Nn;

    __shared__ float4 Ws[16][16];
    __shared__ float4 Xs[16][16];

    const int t = threadIdx.x;
    const int tx = t & 15, ty = t >> 4;
    float acc[4][4] = {};

    const int ktiles = K >> 4;
    float4 wreg = *(const float4*)&Wz[(size_t)ty * M + m0 + tx * 4];
    float4 xreg = *(const float4*)&Xz[(size_t)ty * Nn + n0 + tx * 4];
    for (int kt = 0; kt < ktiles; kt++) {
        Ws[ty][tx] = wreg; Xs[ty][tx] = xreg;
        __syncthreads();
        if (kt + 1 < ktiles) {
            int k0 = (kt + 1) << 4;
            wreg = *(const float4*)&Wz[(size_t)(k0 + ty) * M + m0 + tx * 4];
            xreg = *(const float4*)&Xz[(size_t)(k0 + ty) * Nn + n0 + tx * 4];
        }
        #pragma unroll
        for (int kk = 0; kk < 16; kk++) {
            float4 wf = Ws[kk][ty];
            float4 xf = Xs[kk][tx];
            acc[0][0] = fmaf(wf.x, xf.x, acc[0][0]); acc[0][1] = fmaf(wf.x, xf.y, acc[0][1]);
            acc[0][2] = fmaf(wf.x, xf.z, acc[0][2]); acc[0][3] = fmaf(wf.x, xf.w, acc[0][3]);
            acc[1][0] = fmaf(wf.y, xf.x, acc[1][0]); acc[1][1] = fmaf(wf.y, xf.y, acc[1][1]);
            acc[1][2] = fmaf(wf.y, xf.z, acc[1][2]); acc[1][3] = fmaf(wf.y, xf.w, acc[1][3]);
            acc[2][0] = fmaf(wf.z, xf.x, acc[2][0]); acc[2][1] = fmaf(wf.z, xf.y, acc[2][1]);
            acc[2][2] = fmaf(wf.z, xf.z, acc[2][2]); acc[2][3] = fmaf(wf.z, xf.w, acc[2][3]);
            acc[3][0] = fmaf(wf.w, xf.x, acc[3][0]); acc[3][1] = fmaf(wf.w, xf.y, acc[3][1]);
            acc[3][2] = fmaf(wf.w, xf.z, acc[3][2]); acc[3][3] = fmaf(wf.w, xf.w, acc[3][3]);
        }
        __syncthreads();
    }
    #pragma unroll
    for (int i = 0; i < 4; i++) {
        int m = m0 + ty * 4 + i;
        float e = (ACT == 3) ? extra[m] : 0.f;
        float4 o;
        o.x = act_fn<ACT>(acc[i][0], e); o.y = act_fn<ACT>(acc[i][1], e);
        o.z = act_fn<ACT>(acc[i][2], e); o.w = act_fn<ACT>(acc[i][3], e);
        *(float4*)&Yz[(size_t)m * Nn + n0 + tx * 4] = o;
    }
}

// ---------------- mix GEMM: x5[s][b] = x + xx*(maa_s + W2[s]^T @ t[b,s]) -----------
// z = s*8 + b. Wt = maa_w2 (5,64,768) used natively as (K=64, M=768) per s.
__global__ void __launch_bounds__(256) gemm_mix_k(
    const float* __restrict__ W2, const float* __restrict__ T,
    const float* __restrict__ x,
    const float* __restrict__ p0, const float* __restrict__ p1,
    const float* __restrict__ p2, const float* __restrict__ p3,
    const float* __restrict__ p4)
{
    const int z = blockIdx.z;
    const int s = z >> 3, b = z & 7;
    const int m0 = blockIdx.y * 64;
    const int n0 = blockIdx.x * 64;
    const float* Wz = W2 + (size_t)s * 64 * 768;
    const float* Xz = T + (size_t)b * 320 * Nn + (size_t)s * 64 * Nn;
    float*       Yz = g_x5 + (size_t)z * Cc * Nn;
    const float* xb  = x    + (size_t)b * Cc * Nn;
    const float* xxb = g_xx + (size_t)b * Cc * Nn;
    const float* maa = (s == 0) ? p0 : (s == 1) ? p1 : (s == 2) ? p2 : (s == 3) ? p3 : p4;

    __shared__ float4 Ws[16][16];
    __shared__ float4 Xs[16][16];
    const int t = threadIdx.x;
    const int tx = t & 15, ty = t >> 4;
    float acc[4][4] = {};

    float4 wreg = *(const float4*)&Wz[(size_t)ty * 768 + m0 + tx * 4];
    float4 xreg = *(const float4*)&Xz[(size_t)ty * Nn + n0 + tx * 4];
    for (int kt = 0; kt < 4; kt++) {
        Ws[ty][tx] = wreg; Xs[ty][tx] = xreg;
        __syncthreads();
        if (kt + 1 < 4) {
            int k0 = (kt + 1) << 4;
            wreg = *(const float4*)&Wz[(size_t)(k0 + ty) * 768 + m0 + tx * 4];
            xreg = *(const float4*)&Xz[(size_t)(k0 + ty) * Nn + n0 + tx * 4];
        }
        #pragma unroll
        for (int kk = 0; kk < 16; kk++) {
            float4 wf = Ws[kk][ty];
            float4 xf = Xs[kk][tx];
            acc[0][0] = fmaf(wf.x, xf.x, acc[0][0]); acc[0][1] = fmaf(wf.x, xf.y, acc[0][1]);
            acc[0][2] = fmaf(wf.x, xf.z, acc[0][2]); acc[0][3] = fmaf(wf.x, xf.w, acc[0][3]);
            acc[1][0] = fmaf(wf.y, xf.x, acc[1][0]); acc[1][1] = fmaf(wf.y, xf.y, acc[1][1]);
            acc[1][2] = fmaf(wf.y, xf.z, acc[1][2]); acc[1][3] = fmaf(wf.y, xf.w, acc[1][3]);
            acc[2][0] = fmaf(wf.z, xf.x, acc[2][0]); acc[2][1] = fmaf(wf.z, xf.y, acc[2][1]);
            acc[2][2] = fmaf(wf.z, xf.z, acc[2][2]); acc[2][3] = fmaf(wf.z, xf.w, acc[2][3]);
            acc[3][0] = fmaf(wf.w, xf.x, acc[3][0]); acc[3][1] = fmaf(wf.w, xf.y, acc[3][1]);
            acc[3][2] = fmaf(wf.w, xf.z, acc[3][2]); acc[3][3] = fmaf(wf.w, xf.w, acc[3][3]);
        }
        __syncthreads();
    }
    #pragma unroll
    for (int i = 0; i < 4; i++) {
        int m = m0 + ty * 4 + i;
        size_t off = (size_t)m * Nn + n0 + tx * 4;
        float4 xv  = *(const float4*)&xb[off];
        float4 xxv = *(const float4*)&xxb[off];
        float mc = maa[m];
        float4 o;
        o.x = fmaf(xxv.x, mc + acc[i][0], xv.x);
        o.y = fmaf(xxv.y, mc + acc[i][1], xv.y);
        o.z = fmaf(xxv.z, mc + acc[i][2], xv.z);
        o.w = fmaf(xxv.w, mc + acc[i][3], xv.w);
        *(float4*)&Yz[off] = o;
    }
}

// ---------------- K4: pack r,k,dec,v into (bh, n, j) float4 ------------------------
__global__ void pack_kernel() {
    size_t idx = (size_t)blockIdx.x * 256 + threadIdx.x;
    if (idx >= (size_t)BCN) return;
    int n = (int)(idx & 4095);
    int c = (int)((idx >> 12) % 768);
    int b = (int)(idx / ((size_t)768 * 4096));
    int h = c >> 6, j = c & 63;
    float4 o = make_float4(g_r[idx], g_k[idx], g_dec[idx], g_v[idx]);
    g_rkdv[((size_t)(b * 12 + h) * 4096 + n) * 64 + j] = o;
}

// ---------------- K5: WKV6 sequential scan -----------------------------------------
__global__ void __launch_bounds__(256) scan_kernel(const float* __restrict__ u_in) {
    int bh = blockIdx.x;               // b*12 + h
    int h = bh % 12, b = bh / 12;
    int t = threadIdx.x;
    int jq = t & 3, i = t >> 2;        // thread owns v-index i, k-indices j = jq + 4*jj
    __shared__ float4 buf[2][16][64];
    float S[16], uu[16];
    #pragma unroll
    for (int jj = 0; jj < 16; jj++) { S[jj] = 0.f; uu[jj] = u_in[h * 64 + jq + 4 * jj]; }
    const float4* src = g_rkdv + (size_t)bh * 4096 * 64;
    float* ydst = g_y + (size_t)b * 4096 * 768 + h * 64 + i;
    float4 pre[4];
    #pragma unroll
    for (int q = 0; q < 4; q++) pre[q] = src[t + 256 * q];
    int cur = 0;
    for (int nt = 0; nt < 256; nt++) {
        #pragma unroll
        for (int q = 0; q < 4; q++) ((float4*)buf[cur])[t + 256 * q] = pre[q];
        __syncthreads();
        if (nt + 1 < 256) {
            const float4* nsrc = src + (size_t)(nt + 1) * 1024;
            #pragma unroll
            for (int q = 0; q < 4; q++) pre[q] = nsrc[t + 256 * q];
        }
        #pragma unroll
        for (int s = 0; s < 16; s++) {
            float vi = buf[cur][s][i].w;
            float p = 0.f;
            #pragma unroll
            for (int jj = 0; jj < 16; jj++) {
                float4 f = buf[cur][s][jq + 4 * jj];  // (r, k, dec, v) of channel j
                float kv = f.y * vi;
                float tmp = fmaf(uu[jj], kv, S[jj]);
                p = fmaf(f.x, tmp, p);
                S[jj] = fmaf(f.z, S[jj], kv);
            }
            p += __shfl_xor_sync(0xffffffffu, p, 1);
            p += __shfl_xor_sync(0xffffffffu, p, 2);
            if (jq == 0) ydst[(size_t)(nt * 16 + s) * 768] = p;
        }
        __syncthreads();
        cur ^= 1;
    }
}

// ---------------- K6a: RMS over channel dim ----------------------------------------
__global__ void rms_kernel() {
    int row = blockIdx.x * 8 + (threadIdx.x >> 5);   // b*N + n
    int lane = threadIdx.x & 31;
    const float* yr = g_y + (size_t)row * 768;
    float s = 0.f;
    #pragma unroll
    for (int q = 0; q < 24; q++) { float v = yr[lane + 32 * q]; s += v * v; }
    #pragma unroll
    for (int off = 16; off; off >>= 1) s += __shfl_xor_sync(0xffffffffu, s, off);
    if (lane == 0) g_rms[row] = rsqrtf(s * (1.f / 768.f) + 1e-6f);
}

// ---------------- K6b: normalize + transpose (B,N,C)->(B,C,N) + gate ---------------
__global__ void tgate_kernel(const float* __restrict__ lnw) {
    int b = blockIdx.z;
    int n0 = blockIdx.x * 32, c0 = blockIdx.y * 32;
    __shared__ float tile[32][33];
    int tx = threadIdx.x, ty = threadIdx.y;
    float lw = lnw[c0 + tx];
    for (int r = ty; r < 32; r += 8) {
        int n = n0 + r;
        tile[r][tx] = g_y[((size_t)b * 4096 + n) * 768 + c0 + tx]
                      * g_rms[b * 4096 + n] * lw;
    }
    __syncthreads();
    for (int r = ty; r < 32; r += 8) {
        int c = c0 + r;
        size_t o = ((size_t)b * 768 + c) * 4096 + n0 + tx;
        g_y2[o] = tile[tx][r] * g_gate[o];
    }
}

// ---------------- launch ------------------------------------------------------------
extern "C" void kernel_launch(void* const* d_in, const int* in_sizes, int n_in,
                              void* d_out, int out_size) {
    const float* x        = (const float*)d_in[0];
    const float* maa_x    = (const float*)d_in[1];
    const float* maa_w    = (const float*)d_in[2];
    const float* maa_k    = (const float*)d_in[3];
    const float* maa_v    = (const float*)d_in[4];
    const float* maa_r    = (const float*)d_in[5];
    const float* maa_g    = (const float*)d_in[6];
    const float* maa_w1   = (const float*)d_in[7];
    const float* maa_w2   = (const float*)d_in[8];
    const float* tdecay   = (const float*)d_in[9];
    const float* td_w1    = (const float*)d_in[10];
    const float* td_w2    = (const float*)d_in[11];
    const float* faaaa    = (const float*)d_in[12];
    const float* key_w    = (const float*)d_in[13];
    const float* value_w  = (const float*)d_in[14];
    const float* recept_w = (const float*)d_in[15];
    const float* gate_w   = (const float*)d_in[16];
    const float* out_w    = (const float*)d_in[17];
    const float* ln_x_w   = (const float*)d_in[18];
    float* out = (float*)d_out;

    float *wt_maaw1, *wt_td1, *wt_td2, *wt_r, *wt_k, *wt_v, *wt_g, *wt_o;
    cudaGetSymbolAddress((void**)&wt_maaw1, g_wt_maaw1);
    cudaGetSymbolAddress((void**)&wt_td1,   g_wt_td1);
    cudaGetSymbolAddress((void**)&wt_td2,   g_wt_td2);
    cudaGetSymbolAddress((void**)&wt_r, g_wt_r);
    cudaGetSymbolAddress((void**)&wt_k, g_wt_k);
    cudaGetSymbolAddress((void**)&wt_v, g_wt_v);
    cudaGetSymbolAddress((void**)&wt_g, g_wt_g);
    cudaGetSymbolAddress((void**)&wt_o, g_wt_o);
    float *p_xxx, *p_t, *p_x5, *p_r, *p_k, *p_v, *p_gate, *p_h, *p_dec, *p_y2;
    cudaGetSymbolAddress((void**)&p_xxx, g_xxx);
    cudaGetSymbolAddress((void**)&p_t,   g_t);
    cudaGetSymbolAddress((void**)&p_x5,  g_x5);
    cudaGetSymbolAddress((void**)&p_r,   g_r);
    cudaGetSymbolAddress((void**)&p_k,   g_k);
    cudaGetSymbolAddress((void**)&p_v,   g_v);
    cudaGetSymbolAddress((void**)&p_gate,g_gate);
    cudaGetSymbolAddress((void**)&p_h,   g_h);
    cudaGetSymbolAddress((void**)&p_dec, g_dec);
    cudaGetSymbolAddress((void**)&p_y2,  g_y2);

    dim3 tb32(32, 8);
    // W transposes
    wtrans_kernel<<<dim3(768/32, 320/32, 1), tb32>>>(maa_w1, wt_maaw1, 320, 768);
    wtrans_kernel<<<dim3(768/32, 64/32, 1),  tb32>>>(td_w1,  wt_td1,   64, 768);
    wtrans_kernel<<<dim3(64/32,  768/32, 1), tb32>>>(td_w2,  wt_td2,  768,  64);
    wtrans_kernel<<<dim3(384/32, 384/32, 2), tb32>>>(recept_w, wt_r, 384, 384);
    wtrans_kernel<<<dim3(384/32, 384/32, 2), tb32>>>(key_w,    wt_k, 384, 384);
    wtrans_kernel<<<dim3(384/32, 384/32, 2), tb32>>>(value_w,  wt_v, 384, 384);
    wtrans_kernel<<<dim3(384/32, 384/32, 2), tb32>>>(gate_w,   wt_g, 384, 384);
    wtrans_kernel<<<dim3(384/32, 384/32, 2), tb32>>>(out_w,    wt_o, 384, 384);

    // shift
    shift_kernel<<<(BCN + 255) / 256, 256>>>(x, maa_x);

    // t = tanh(maa_w1 @ xxx)   (M=320, K=768, z=B)
    gemm_k<1><<<dim3(64, 5, 8), 256>>>(wt_maaw1, p_xxx, p_t, 320, 768, 1, nullptr);

    // x5 slices (z = s*8+b, 40)
    gemm_mix_k<<<dim3(64, 12, 40), 256>>>(maa_w2, p_t, x,
                                          maa_w, maa_k, maa_v, maa_r, maa_g);

    // grouped convs (M=384, K=384, z = b*2+g = 16)
    gemm_k<0><<<dim3(64, 6, 16), 256>>>(wt_r, p_x5 + (size_t)3 * BCN, p_r,    384, 384, 2, nullptr);
    gemm_k<0><<<dim3(64, 6, 16), 256>>>(wt_k, p_x5 + (size_t)1 * BCN, p_k,    384, 384, 2, nullptr);
    gemm_k<0><<<dim3(64, 6, 16), 256>>>(wt_v, p_x5 + (size_t)2 * BCN, p_v,    384, 384, 2, nullptr);
    gemm_k<2><<<dim3(64, 6, 16), 256>>>(wt_g, p_x5 + (size_t)4 * BCN, p_gate, 384, 384, 2, nullptr);

    // decay MLP: h = tanh(td_w1 @ xw); dec = exp(-exp(td + td_w2 @ h))
    gemm_k<1><<<dim3(64, 1, 8),  256>>>(wt_td1, p_x5, p_h, 64, 768, 1, nullptr);
    gemm_k<3><<<dim3(64, 12, 8), 256>>>(wt_td2, p_h, p_dec, 768, 64, 1, tdecay);

    // pack + scan
    pack_kernel<<<(BCN + 255) / 256, 256>>>();
    scan_kernel<<<96, 256>>>(faaaa);

    // rmsnorm + transpose + gate
    rms_kernel<<<(Bb * Nn) / 8, 256>>>();
    tgate_kernel<<<dim3(128, 24, 8), tb32>>>(ln_x_w);

    // final grouped conv -> out
    gemm_k<0><<<dim3(64, 6, 16), 256>>>(wt_o, p_y2, out, 384, 384, 2, nullptr);
}

// round 6
// speedup vs baseline: 1.4353x; 1.4353x over previous
#include <cuda_runtime.h>
#include <cuda_bf16.h>
#include <cstdint>
#include <cstddef>

#define Bb 8
#define Cc 768
#define Nn 4096
#define BCN (Bb*Cc*Nn)   // 25165824

// ---------------- scratch (static device globals) ---------------------------------
__device__ __align__(16) float g_xx [BCN];
__device__ __align__(16) float g_xxx[BCN];
__device__ __align__(16) float g_t  [Bb*384*Nn];          // padded 320->384 rows
__device__ __align__(16) float g_x5 [5u*(size_t)BCN];     // s: 0=xw 1=xk 2=xv 3=xr 4=xg
__device__ __align__(16) float g_r  [BCN];
__device__ __align__(16) float g_k  [BCN];
__device__ __align__(16) float g_v  [BCN];
__device__ __align__(16) float g_gate[BCN];
__device__ __align__(16) float g_h  [Bb*64*Nn];
__device__ __align__(16) float g_dec[BCN];
__device__ float4 g_rkdv[(size_t)Bb*12*Nn*64];
__device__ __align__(16) float g_y  [BCN];                // (B, N, C)
__device__ __align__(16) float g_y2 [BCN];                // (B, C, N)
__device__ float g_rms[Bb*Nn];
__device__ float g_wt_td1[768*64];                        // fp32 path for decay1
// tf32-prepped weights: layout [z][kt][m][perm(k)]  (16 floats per (kt,m))
__device__ __align__(16) float g_wp_t  [48*384*16];       // maa_w1 (Mp=384,K=768)
__device__ __align__(16) float g_wp_w2 [5*4*768*16];      // maa_w2 (M=768,K=64) x5
__device__ __align__(16) float g_wp_r[2*24*384*16];
__device__ __align__(16) float g_wp_k[2*24*384*16];
__device__ __align__(16) float g_wp_v[2*24*384*16];
__device__ __align__(16) float g_wp_g[2*24*384*16];
__device__ __align__(16) float g_wp_o[2*24*384*16];
__device__ __align__(16) float g_wp_td2[4*768*16];        // td_w2 (M=768,K=64)

// ---------------- tf32 helpers -----------------------------------------------------
__device__ __forceinline__ float cvt_tf32(float x) {
    uint32_t u; asm("cvt.rna.tf32.f32 %0, %1;" : "=r"(u) : "f"(x));
    return __uint_as_float(u);
}
__device__ __forceinline__ void mma8(float* d, float a0, float a1, float a2, float a3,
                                     float b0, float b1) {
    asm("mma.sync.aligned.m16n8k8.row.col.f32.tf32.tf32.f32 "
        "{%0,%1,%2,%3}, {%4,%5,%6,%7}, {%8,%9}, {%0,%1,%2,%3};"
        : "+f"(d[0]), "+f"(d[1]), "+f"(d[2]), "+f"(d[3])
        : "r"(__float_as_uint(a0)), "r"(__float_as_uint(a1)),
          "r"(__float_as_uint(a2)), "r"(__float_as_uint(a3)),
          "r"(__float_as_uint(b0)), "r"(__float_as_uint(b1)));
}

// ---------------- weight prep: (M,K) or (K,M) -> [kt][m][perm(k)] tf32 -------------
__global__ void prep_w(const float* __restrict__ src, float* __restrict__ dst,
                       int M, int Mp, int K, int trans, int nz) {
    size_t idx = (size_t)blockIdx.x * 256 + threadIdx.x;
    size_t per_z = (size_t)Mp * K;
    if (idx >= per_z * nz) return;
    int z = (int)(idx / per_z);
    size_t rem = idx - (size_t)z * per_z;
    int m = (int)(rem / K), k = (int)(rem % K);
    float v = 0.f;
    if (m < M) v = trans ? src[(size_t)z*M*K + (size_t)k*M + m]
                         : src[(size_t)z*M*K + (size_t)m*K + k];
    v = cvt_tf32(v);
    int kt = k >> 4, kk = k & 15;
    int p = (kk & 3) * 4 + (kk >> 2);
    dst[(((size_t)z*(K>>4) + kt)*Mp + m)*16 + p] = v;
}

// ---------------- wtrans for fp32 decay1 path --------------------------------------
__global__ void wtrans_kernel(const float* __restrict__ W, float* __restrict__ Wt,
                              int M, int K) {
    __shared__ float tile[32][33];
    int m0 = blockIdx.y * 32, k0 = blockIdx.x * 32;
    int tx = threadIdx.x, ty = threadIdx.y;
    for (int r = ty; r < 32; r += 8) {
        int m = m0 + r, k = k0 + tx;
        tile[r][tx] = (m < M && k < K) ? W[(size_t)m * K + k] : 0.f;
    }
    __syncthreads();
    for (int r = ty; r < 32; r += 8) {
        int k = k0 + r, m = m0 + tx;
        if (k < K && m < M) Wt[(size_t)k * M + m] = tile[tx][r];
    }
}

// ---------------- K1: q_shift + xx + xxx -------------------------------------------
__global__ void shift_kernel(const float* __restrict__ x, const float* __restrict__ maa_x) {
    size_t idx = (size_t)blockIdx.x * 256 + threadIdx.x;
    if (idx >= (size_t)BCN) return;
    int n = (int)(idx & (Nn - 1));
    int c = (int)((idx >> 12) % Cc);
    int w = n & 63, hh = n >> 6;
    float xv = x[idx], s;
    int mode = c / 192;
    if (mode == 0)      s = (w  > 0 ) ? x[idx - 1 ] : 0.f;
    else if (mode == 1) s = (w  < 63) ? x[idx + 1 ] : 0.f;
    else if (mode == 2) s = (hh > 0 ) ? x[idx - 64] : 0.f;
    else                s = (hh < 63) ? x[idx + 64] : 0.f;
    float d = s - xv;
    g_xx[idx]  = d;
    g_xxx[idx] = fmaf(d, maa_x[c], xv);
}

// ---------------- TF32 tensor-core GEMM --------------------------------------------
// Y[z] = act( Wp[z]^T-equivalent @ X[z] ),  Wp in [kt][m][perm] layout.
// ACT: 0 none, 1 tanh, 2 silu, 3 decay exp(-exp(extra[m]+v)), 4 mix fuse.
// Block 128 thr, tile 128(M) x 128(N), warp 64x64, BK=16.
template<int ACT>
__global__ void __launch_bounds__(128) gemm_tc(
    const float* __restrict__ Wp, const float* __restrict__ Xin,
    float* __restrict__ Y, int Mp, int K, int wmod,
    const float* __restrict__ extra, const float* __restrict__ xin,
    const float* __restrict__ q0, const float* __restrict__ q1,
    const float* __restrict__ q2, const float* __restrict__ q3,
    const float* __restrict__ q4)
{
    const int z   = blockIdx.z;
    const int m0g = blockIdx.y * 128;
    const int n0g = blockIdx.x * 128;
    const int ktiles = K >> 4;

    const float* Wz; const float* Xz; float* Yz;
    const float* maa = nullptr; const float* xb = nullptr; const float* xxb = nullptr;
    if (ACT == 4) {
        int s = z >> 3, b = z & 7;
        Wz = Wp + (size_t)s * Mp * K;
        Xz = Xin + (size_t)b * 384 * Nn + (size_t)s * 64 * Nn;
        Yz = Y + (size_t)z * Mp * Nn;
        maa = (s==0)?q0:(s==1)?q1:(s==2)?q2:(s==3)?q3:q4;
        xb  = xin + (size_t)b * Cc * Nn;
        xxb = g_xx + (size_t)b * Cc * Nn;
    } else {
        Wz = Wp + (size_t)(z % wmod) * Mp * K;
        Xz = Xin + (size_t)z * K * Nn;
        Yz = Y + (size_t)z * Mp * Nn;
    }

    __shared__ float4 As4[2][128][4];
    __shared__ __align__(16) float Bs[2][16][136];

    const int t = threadIdx.x;
    const int lane = t & 31, wid = t >> 5;
    const int wm = wid >> 1, wn = wid & 1;
    const int r = lane >> 2, c = lane & 3;

    float acc[4][8][4];
    #pragma unroll
    for (int i = 0; i < 4; i++)
        #pragma unroll
        for (int j = 0; j < 8; j++)
            #pragma unroll
            for (int q = 0; q < 4; q++) acc[i][j][q] = 0.f;

    const float4* Wz4 = (const float4*)Wz;
    float4 aR[4], bR[4];

    // initial prefetch (kt=0)
    #pragma unroll
    for (int q = 0; q < 4; q++) {
        int i = q * 128 + t; int m = i >> 2, w = i & 3;
        aR[q] = Wz4[((size_t)0 * Mp + m0g + m) * 4 + w];
    }
    #pragma unroll
    for (int q = 0; q < 4; q++) {
        int i = q * 128 + t; int k = i >> 5, n4 = i & 31;
        bR[q] = *(const float4*)&Xz[(size_t)k * Nn + n0g + n4 * 4];
    }

    int buf = 0;
    for (int kt = 0; kt < ktiles; kt++) {
        // store staged tiles
        #pragma unroll
        for (int q = 0; q < 4; q++) {
            int i = q * 128 + t; int m = i >> 2, w = i & 3;
            As4[buf][m][w] = aR[q];
        }
        #pragma unroll
        for (int q = 0; q < 4; q++) {
            int i = q * 128 + t; int k = i >> 5, n4 = i & 31;
            float4 v = bR[q];
            v.x = cvt_tf32(v.x); v.y = cvt_tf32(v.y);
            v.z = cvt_tf32(v.z); v.w = cvt_tf32(v.w);
            *(float4*)&Bs[buf][k][n4 * 4] = v;
        }
        __syncthreads();
        if (kt + 1 < ktiles) {
            #pragma unroll
            for (int q = 0; q < 4; q++) {
                int i = q * 128 + t; int m = i >> 2, w = i & 3;
                aR[q] = Wz4[((size_t)(kt + 1) * Mp + m0g + m) * 4 + w];
            }
            #pragma unroll
            for (int q = 0; q < 4; q++) {
                int i = q * 128 + t; int k = i >> 5, n4 = i & 31;
                bR[q] = *(const float4*)&Xz[(size_t)((kt + 1) * 16 + k) * Nn + n0g + n4 * 4];
            }
        }
        // compute on buf
        float4 Alo[4], Ahi[4];
        #pragma unroll
        for (int mf = 0; mf < 4; mf++) {
            Alo[mf] = As4[buf][wm * 64 + mf * 16 + r][c];
            Ahi[mf] = As4[buf][wm * 64 + mf * 16 + 8 + r][c];
        }
        #pragma unroll
        for (int ks = 0; ks < 2; ks++) {
            #pragma unroll
            for (int nf = 0; nf < 8; nf++) {
                int col = wn * 64 + nf * 8 + r;
                float b0 = Bs[buf][c + 8 * ks][col];
                float b1 = Bs[buf][c + 4 + 8 * ks][col];
                #pragma unroll
                for (int mf = 0; mf < 4; mf++) {
                    if (ks == 0)
                        mma8(acc[mf][nf], Alo[mf].x, Ahi[mf].x, Alo[mf].y, Ahi[mf].y, b0, b1);
                    else
                        mma8(acc[mf][nf], Alo[mf].z, Ahi[mf].z, Alo[mf].w, Ahi[mf].w, b0, b1);
                }
            }
        }
        __syncthreads();
        buf ^= 1;
    }

    // epilogue
    #pragma unroll
    for (int mf = 0; mf < 4; mf++) {
        int rr0 = m0g + wm * 64 + mf * 16 + r;
        #pragma unroll
        for (int half = 0; half < 2; half++) {
            int rr = rr0 + half * 8;
            float e  = (ACT == 3) ? extra[rr] : 0.f;
            float mc = (ACT == 4) ? maa[rr]   : 0.f;
            #pragma unroll
            for (int nf = 0; nf < 8; nf++) {
                int nc = n0g + wn * 64 + nf * 8 + c * 2;
                float v0 = acc[mf][nf][half * 2 + 0];
                float v1 = acc[mf][nf][half * 2 + 1];
                size_t off = (size_t)rr * Nn + nc;
                if (ACT == 1) { v0 = tanhf(v0); v1 = tanhf(v1); }
                else if (ACT == 2) { v0 = v0 / (1.f + expf(-v0)); v1 = v1 / (1.f + expf(-v1)); }
                else if (ACT == 3) { v0 = expf(-expf(e + v0)); v1 = expf(-expf(e + v1)); }
                else if (ACT == 4) {
                    float2 xv  = *(const float2*)&xb[off];
                    float2 xxv = *(const float2*)&xxb[off];
                    v0 = fmaf(xxv.x, mc + v0, xv.x);
                    v1 = fmaf(xxv.y, mc + v1, xv.y);
                }
                *(float2*)&Yz[off] = make_float2(v0, v1);
            }
        }
    }
}

// ---------------- fp32 GEMM (kept for small decay1) --------------------------------
template<int ACT>
__global__ void __launch_bounds__(256) gemm_k(
    const float* __restrict__ Wt, const float* __restrict__ X,
    float* __restrict__ Y, int M, int K, int wmod,
    const float* __restrict__ extra)
{
    const int z  = blockIdx.z;
    const int m0 = blockIdx.y * 64;
    const int n0 = blockIdx.x * 64;
    const float* Wz = Wt + (size_t)(z % wmod) * M * K;
    const float* Xz = X  + (size_t)z * K * Nn;
    float*       Yz = Y  + (size_t)z * M * Nn;

    __shared__ float4 Ws[16][16];
    __shared__ float4 Xs[16][16];
    const int t = threadIdx.x;
    const int tx = t & 15, ty = t >> 4;
    float acc[4][4] = {};

    const int ktiles = K >> 4;
    float4 wreg = *(const float4*)&Wz[(size_t)ty * M + m0 + tx * 4];
    float4 xreg = *(const float4*)&Xz[(size_t)ty * Nn + n0 + tx * 4];
    for (int kt = 0; kt < ktiles; kt++) {
        Ws[ty][tx] = wreg; Xs[ty][tx] = xreg;
        __syncthreads();
        if (kt + 1 < ktiles) {
            int k0 = (kt + 1) << 4;
            wreg = *(const float4*)&Wz[(size_t)(k0 + ty) * M + m0 + tx * 4];
            xreg = *(const float4*)&Xz[(size_t)(k0 + ty) * Nn + n0 + tx * 4];
        }
        #pragma unroll
        for (int kk = 0; kk < 16; kk++) {
            float4 wf = Ws[kk][ty];
            float4 xf = Xs[kk][tx];
            acc[0][0] = fmaf(wf.x, xf.x, acc[0][0]); acc[0][1] = fmaf(wf.x, xf.y, acc[0][1]);
            acc[0][2] = fmaf(wf.x, xf.z, acc[0][2]); acc[0][3] = fmaf(wf.x, xf.w, acc[0][3]);
            acc[1][0] = fmaf(wf.y, xf.x, acc[1][0]); acc[1][1] = fmaf(wf.y, xf.y, acc[1][1]);
            acc[1][2] = fmaf(wf.y, xf.z, acc[1][2]); acc[1][3] = fmaf(wf.y, xf.w, acc[1][3]);
            acc[2][0] = fmaf(wf.z, xf.x, acc[2][0]); acc[2][1] = fmaf(wf.z, xf.y, acc[2][1]);
            acc[2][2] = fmaf(wf.z, xf.z, acc[2][2]); acc[2][3] = fmaf(wf.z, xf.w, acc[2][3]);
            acc[3][0] = fmaf(wf.w, xf.x, acc[3][0]); acc[3][1] = fmaf(wf.w, xf.y, acc[3][1]);
            acc[3][2] = fmaf(wf.w, xf.z, acc[3][2]); acc[3][3] = fmaf(wf.w, xf.w, acc[3][3]);
        }
        __syncthreads();
    }
    #pragma unroll
    for (int i = 0; i < 4; i++) {
        int m = m0 + ty * 4 + i;
        float4 o;
        float a0 = acc[i][0], a1 = acc[i][1], a2 = acc[i][2], a3 = acc[i][3];
        if (ACT == 1) { a0 = tanhf(a0); a1 = tanhf(a1); a2 = tanhf(a2); a3 = tanhf(a3); }
        o.x = a0; o.y = a1; o.z = a2; o.w = a3;
        *(float4*)&Yz[(size_t)m * Nn + n0 + tx * 4] = o;
    }
}

// ---------------- K4: pack r,k,dec,v -----------------------------------------------
__global__ void pack_kernel() {
    size_t idx = (size_t)blockIdx.x * 256 + threadIdx.x;
    if (idx >= (size_t)BCN) return;
    int n = (int)(idx & 4095);
    int c = (int)((idx >> 12) % 768);
    int b = (int)(idx / ((size_t)768 * 4096));
    int h = c >> 6, j = c & 63;
    float4 o = make_float4(g_r[idx], g_k[idx], g_dec[idx], g_v[idx]);
    g_rkdv[((size_t)(b * 12 + h) * 4096 + n) * 64 + j] = o;
}

// ---------------- K5: WKV6 sequential scan -----------------------------------------
__global__ void __launch_bounds__(256) scan_kernel(const float* __restrict__ u_in) {
    int bh = blockIdx.x;
    int h = bh % 12, b = bh / 12;
    int t = threadIdx.x;
    int jq = t & 3, i = t >> 2;
    __shared__ float4 buf[2][16][64];
    float S[16], uu[16];
    #pragma unroll
    for (int jj = 0; jj < 16; jj++) { S[jj] = 0.f; uu[jj] = u_in[h * 64 + jq + 4 * jj]; }
    const float4* src = g_rkdv + (size_t)bh * 4096 * 64;
    float* ydst = g_y + (size_t)b * 4096 * 768 + h * 64 + i;
    float4 pre[4];
    #pragma unroll
    for (int q = 0; q < 4; q++) pre[q] = src[t + 256 * q];
    int cur = 0;
    for (int nt = 0; nt < 256; nt++) {
        #pragma unroll
        for (int q = 0; q < 4; q++) ((float4*)buf[cur])[t + 256 * q] = pre[q];
        __syncthreads();
        if (nt + 1 < 256) {
            const float4* nsrc = src + (size_t)(nt + 1) * 1024;
            #pragma unroll
            for (int q = 0; q < 4; q++) pre[q] = nsrc[t + 256 * q];
        }
        #pragma unroll
        for (int s = 0; s < 16; s++) {
            float vi = buf[cur][s][i].w;
            float p = 0.f;
            #pragma unroll
            for (int jj = 0; jj < 16; jj++) {
                float4 f = buf[cur][s][jq + 4 * jj];
                float kv = f.y * vi;
                float tmp = fmaf(uu[jj], kv, S[jj]);
                p = fmaf(f.x, tmp, p);
                S[jj] = fmaf(f.z, S[jj], kv);
            }
            p += __shfl_xor_sync(0xffffffffu, p, 1);
            p += __shfl_xor_sync(0xffffffffu, p, 2);
            if (jq == 0) ydst[(size_t)(nt * 16 + s) * 768] = p;
        }
        __syncthreads();
        cur ^= 1;
    }
}

// ---------------- K6a: RMS over channel dim ----------------------------------------
__global__ void rms_kernel() {
    int row = blockIdx.x * 8 + (threadIdx.x >> 5);
    int lane = threadIdx.x & 31;
    const float* yr = g_y + (size_t)row * 768;
    float s = 0.f;
    #pragma unroll
    for (int q = 0; q < 24; q++) { float v = yr[lane + 32 * q]; s += v * v; }
    #pragma unroll
    for (int off = 16; off; off >>= 1) s += __shfl_xor_sync(0xffffffffu, s, off);
    if (lane == 0) g_rms[row] = rsqrtf(s * (1.f / 768.f) + 1e-6f);
}

// ---------------- K6b: normalize + transpose + gate --------------------------------
__global__ void tgate_kernel(const float* __restrict__ lnw) {
    int b = blockIdx.z;
    int n0 = blockIdx.x * 32, c0 = blockIdx.y * 32;
    __shared__ float tile[32][33];
    int tx = threadIdx.x, ty = threadIdx.y;
    float lw = lnw[c0 + tx];
    for (int r = ty; r < 32; r += 8) {
        int n = n0 + r;
        tile[r][tx] = g_y[((size_t)b * 4096 + n) * 768 + c0 + tx]
                      * g_rms[b * 4096 + n] * lw;
    }
    __syncthreads();
    for (int r = ty; r < 32; r += 8) {
        int c = c0 + r;
        size_t o = ((size_t)b * 768 + c) * 4096 + n0 + tx;
        g_y2[o] = tile[tx][r] * g_gate[o];
    }
}

// ---------------- launch ------------------------------------------------------------
extern "C" void kernel_launch(void* const* d_in, const int* in_sizes, int n_in,
                              void* d_out, int out_size) {
    const float* x        = (const float*)d_in[0];
    const float* maa_x    = (const float*)d_in[1];
    const float* maa_w    = (const float*)d_in[2];
    const float* maa_k    = (const float*)d_in[3];
    const float* maa_v    = (const float*)d_in[4];
    const float* maa_r    = (const float*)d_in[5];
    const float* maa_g    = (const float*)d_in[6];
    const float* maa_w1   = (const float*)d_in[7];
    const float* maa_w2   = (const float*)d_in[8];
    const float* tdecay   = (const float*)d_in[9];
    const float* td_w1    = (const float*)d_in[10];
    const float* td_w2    = (const float*)d_in[11];
    const float* faaaa    = (const float*)d_in[12];
    const float* key_w    = (const float*)d_in[13];
    const float* value_w  = (const float*)d_in[14];
    const float* recept_w = (const float*)d_in[15];
    const float* gate_w   = (const float*)d_in[16];
    const float* out_w    = (const float*)d_in[17];
    const float* ln_x_w   = (const float*)d_in[18];
    float* out = (float*)d_out;

    float *wp_t, *wp_w2, *wp_r, *wp_k, *wp_v, *wp_g, *wp_o, *wp_td2, *wt_td1;
    cudaGetSymbolAddress((void**)&wp_t,   g_wp_t);
    cudaGetSymbolAddress((void**)&wp_w2,  g_wp_w2);
    cudaGetSymbolAddress((void**)&wp_r,   g_wp_r);
    cudaGetSymbolAddress((void**)&wp_k,   g_wp_k);
    cudaGetSymbolAddress((void**)&wp_v,   g_wp_v);
    cudaGetSymbolAddress((void**)&wp_g,   g_wp_g);
    cudaGetSymbolAddress((void**)&wp_o,   g_wp_o);
    cudaGetSymbolAddress((void**)&wp_td2, g_wp_td2);
    cudaGetSymbolAddress((void**)&wt_td1, g_wt_td1);
    float *p_xxx, *p_t, *p_x5, *p_r, *p_k, *p_v, *p_gate, *p_h, *p_dec, *p_y2;
    cudaGetSymbolAddress((void**)&p_xxx, g_xxx);
    cudaGetSymbolAddress((void**)&p_t,   g_t);
    cudaGetSymbolAddress((void**)&p_x5,  g_x5);
    cudaGetSymbolAddress((void**)&p_r,   g_r);
    cudaGetSymbolAddress((void**)&p_k,   g_k);
    cudaGetSymbolAddress((void**)&p_v,   g_v);
    cudaGetSymbolAddress((void**)&p_gate,g_gate);
    cudaGetSymbolAddress((void**)&p_h,   g_h);
    cudaGetSymbolAddress((void**)&p_dec, g_dec);
    cudaGetSymbolAddress((void**)&p_y2,  g_y2);

    // weight prep (tf32 permuted layouts)
    auto PREP = [&](const float* src, float* dst, int M, int Mp, int K, int tr, int nz) {
        size_t tot = (size_t)nz * Mp * K;
        prep_w<<<(unsigned)((tot + 255) / 256), 256>>>(src, dst, M, Mp, K, tr, nz);
    };
    PREP(maa_w1,   wp_t,   320, 384, 768, 0, 1);
    PREP(maa_w2,   wp_w2,  768, 768,  64, 1, 5);
    PREP(recept_w, wp_r,   384, 384, 384, 0, 2);
    PREP(key_w,    wp_k,   384, 384, 384, 0, 2);
    PREP(value_w,  wp_v,   384, 384, 384, 0, 2);
    PREP(gate_w,   wp_g,   384, 384, 384, 0, 2);
    PREP(out_w,    wp_o,   384, 384, 384, 0, 2);
    PREP(td_w2,    wp_td2, 768, 768,  64, 0, 1);
    wtrans_kernel<<<dim3(768/32, 64/32, 1), dim3(32, 8)>>>(td_w1, wt_td1, 64, 768);

    // shift
    shift_kernel<<<(BCN + 255) / 256, 256>>>(x, maa_x);

    // t = tanh(maa_w1 @ xxx)   (Mp=384 padded, K=768, z=8)
    gemm_tc<1><<<dim3(32, 3, 8), 128>>>(wp_t, p_xxx, p_t, 384, 768, 1,
                                        nullptr, nullptr, nullptr, nullptr, nullptr, nullptr, nullptr);

    // x5 = x + xx*(maa + W2 @ t)   (M=768, K=64, z=40)
    gemm_tc<4><<<dim3(32, 6, 40), 128>>>(wp_w2, p_t, p_x5, 768, 64, 5,
                                         nullptr, x, maa_w, maa_k, maa_v, maa_r, maa_g);

    // grouped convs (M=384, K=384, z=16)
    gemm_tc<0><<<dim3(32, 3, 16), 128>>>(wp_r, p_x5 + (size_t)3 * BCN, p_r,    384, 384, 2,
                                         nullptr, nullptr, nullptr, nullptr, nullptr, nullptr, nullptr);
    gemm_tc<0><<<dim3(32, 3, 16), 128>>>(wp_k, p_x5 + (size_t)1 * BCN, p_k,    384, 384, 2,
                                         nullptr, nullptr, nullptr, nullptr, nullptr, nullptr, nullptr);
    gemm_tc<0><<<dim3(32, 3, 16), 128>>>(wp_v, p_x5 + (size_t)2 * BCN, p_v,    384, 384, 2,
                                         nullptr, nullptr, nullptr, nullptr, nullptr, nullptr, nullptr);
    gemm_tc<2><<<dim3(32, 3, 16), 128>>>(wp_g, p_x5 + (size_t)4 * BCN, p_gate, 384, 384, 2,
                                         nullptr, nullptr, nullptr, nullptr, nullptr, nullptr, nullptr);

    // decay MLP: h = tanh(td_w1 @ xw)  (fp32, M=64);  dec = exp(-exp(td + td_w2 @ h))
    gemm_k<1><<<dim3(64, 1, 8), 256>>>(wt_td1, p_x5, p_h, 64, 768, 1, nullptr);
    gemm_tc<3><<<dim3(32, 6, 8), 128>>>(wp_td2, p_h, p_dec, 768, 64, 1,
                                        tdecay, nullptr, nullptr, nullptr, nullptr, nullptr, nullptr);

    // pack + scan
    pack_kernel<<<(BCN + 255) / 256, 256>>>();
    scan_kernel<<<96, 256>>>(faaaa);

    // rmsnorm + transpose + gate
    rms_kernel<<<(Bb * Nn) / 8, 256>>>();
    tgate_kernel<<<dim3(128, 24, 8), dim3(32, 8)>>>(ln_x_w);

    // final grouped conv -> out
    gemm_tc<0><<<dim3(32, 3, 16), 128>>>(wp_o, p_y2, out, 384, 384, 2,
                                         nullptr, nullptr, nullptr, nullptr, nullptr, nullptr, nullptr);
}

// round 9
// speedup vs baseline: 1.5593x; 1.0864x over previous
#include <cuda_runtime.h>
#include <cuda_fp16.h>
#include <cstdint>
#include <cstddef>

#define Bb 8
#define Cc 768
#define Nn 4096
#define TOK (Bb*Nn)
#define BCN (Bb*Cc*Nn)   // 25165824

// ---------------- scratch (static device globals) ---------------------------------
__device__ __align__(16) float g_xx [BCN];
__device__ __align__(16) float g_xxx[BCN];
__device__ __align__(16) float g_t  [Bb*384*Nn];
__device__ __align__(16) float g_x5 [5u*(size_t)BCN];   // s: 0=xw 1=xk 2=xv 3=xr 4=xg
__device__ __align__(16) float g_r  [BCN];
__device__ __align__(16) float g_k  [BCN];
__device__ __align__(16) float g_v  [BCN];
__device__ __align__(16) float g_gate[BCN];
__device__ __align__(16) float g_h  [(size_t)Bb*128*Nn];  // padded M=128
__device__ __align__(16) float g_dec[BCN];
__device__ float4 g_rkdv[(size_t)Bb*12*Nn*64];
__device__ __align__(16) float g_y  [BCN];
__device__ __align__(16) float g_y2 [BCN];
__device__ float g_rms[TOK];
// fp16 fragment-packed weights: [z][kt][mfr][lane][4] uint32 (half2)
__device__ __align__(16) uint32_t g_wh_t  [48*24*128];      // maa_w1 (Mp=384, K=768)
__device__ __align__(16) uint32_t g_wh_w2 [5*4*48*128];     // maa_w2 (Mp=768, K=64)
__device__ __align__(16) uint32_t g_wh_r  [2*24*24*128];
__device__ __align__(16) uint32_t g_wh_k  [2*24*24*128];
__device__ __align__(16) uint32_t g_wh_v  [2*24*24*128];
__device__ __align__(16) uint32_t g_wh_g  [2*24*24*128];
__device__ __align__(16) uint32_t g_wh_o  [2*24*24*128];
__device__ __align__(16) uint32_t g_wh_td1[48*8*128];       // td_w1 (Mp=128, K=768)
__device__ __align__(16) uint32_t g_wh_td2[4*48*128];       // td_w2 (Mp=768, K=64)

// ---------------- asm helpers ------------------------------------------------------
__device__ __forceinline__ uint32_t s2u(const void* p) {
    uint32_t a;
    asm("{ .reg .u64 t; cvta.to.shared.u64 t, %1; cvt.u32.u64 %0, t; }" : "=r"(a) : "l"(p));
    return a;
}
__device__ __forceinline__ void mma16(float* d, const uint4& a, uint32_t b0, uint32_t b1) {
    asm volatile("mma.sync.aligned.m16n8k16.row.col.f32.f16.f16.f32 "
        "{%0,%1,%2,%3}, {%4,%5,%6,%7}, {%8,%9}, {%0,%1,%2,%3};"
        : "+f"(d[0]), "+f"(d[1]), "+f"(d[2]), "+f"(d[3])
        : "r"(a.x), "r"(a.y), "r"(a.z), "r"(a.w), "r"(b0), "r"(b1));
}
__device__ __forceinline__ void ldmB(uint32_t& b0, uint32_t& b1, uint32_t addr) {
    asm volatile("ldmatrix.sync.aligned.m8n8.x2.trans.shared.b16 {%0,%1}, [%2];"
        : "=r"(b0), "=r"(b1) : "r"(addr));
}

// ---------------- weight prep: fragment-packed fp16 --------------------------------
// dst[((z*KT + kt)*MFR + mfr)*128 + lane*4 + r] = half2(W[m][k], W[m][k+1])
// r=0:(row,k) r=1:(row+8,k) r=2:(row,k+8) r=3:(row+8,k+8); row=lane>>2, k=(lane&3)*2
__global__ void prep_wh(const float* __restrict__ src, uint32_t* __restrict__ dst,
                        int M, int Mp, int K, int trans, int nz) {
    size_t idx = (size_t)blockIdx.x * 256 + threadIdx.x;
    int KT = K >> 4, MFR = Mp >> 4;
    size_t per_z = (size_t)KT * MFR * 128;
    if (idx >= per_z * nz) return;
    int z = (int)(idx / per_z);
    size_t rem = idx - (size_t)z * per_z;
    int kt  = (int)(rem / (MFR * 128));
    int r2  = (int)(rem % (MFR * 128));
    int mfr = r2 >> 7;
    int li  = r2 & 127;
    int lane = li >> 2, r = li & 3;
    int m = mfr * 16 + (lane >> 2) + ((r & 1) << 3);
    int k = kt * 16 + (lane & 3) * 2 + ((r >> 1) << 3);
    float f0 = 0.f, f1 = 0.f;
    if (m < M) {
        const float* sz = src + (size_t)z * M * K;
        if (trans) { f0 = sz[(size_t)k * M + m]; f1 = sz[(size_t)(k + 1) * M + m]; }
        else       { f0 = sz[(size_t)m * K + k]; f1 = sz[(size_t)m * K + k + 1]; }
    }
    __half2 h = __floats2half2_rn(f0, f1);
    dst[idx] = *(uint32_t*)&h;
}

// ---------------- K1: q_shift + xx + xxx -------------------------------------------
__global__ void shift_kernel(const float* __restrict__ x, const float* __restrict__ maa_x) {
    size_t idx = (size_t)blockIdx.x * 256 + threadIdx.x;
    if (idx >= (size_t)BCN) return;
    int n = (int)(idx & (Nn - 1));
    int c = (int)((idx >> 12) % Cc);
    int w = n & 63, hh = n >> 6;
    float xv = x[idx], s;
    int mode = c / 192;
    if (mode == 0)      s = (w  > 0 ) ? x[idx - 1 ] : 0.f;
    else if (mode == 1) s = (w  < 63) ? x[idx + 1 ] : 0.f;
    else if (mode == 2) s = (hh > 0 ) ? x[idx - 64] : 0.f;
    else                s = (hh < 63) ? x[idx + 64] : 0.f;
    float d = s - xv;
    g_xx[idx]  = d;
    g_xxx[idx] = fmaf(d, maa_x[c], xv);
}

// ---------------- fp16 tensor-core GEMM --------------------------------------------
// Y[z](Mp, Nn) = act( W[z] @ X[z] ).  256 thr, 8 warps, block 128x128, warp 64x32.
// ACT: 0 none, 1 tanh, 2 silu, 3 decay exp(-exp(extra[m]+v)), 4 mix fuse.
template<int ACT>
__global__ void __launch_bounds__(256) gemm_h(
    const uint32_t* __restrict__ Wp, const float* __restrict__ X,
    float* __restrict__ Y, int Mp, int K, int wmod,
    long long sXz, long long sYz,
    const float* __restrict__ extra, const float* __restrict__ xin,
    const float* __restrict__ q0, const float* __restrict__ q1,
    const float* __restrict__ q2, const float* __restrict__ q3,
    const float* __restrict__ q4)
{
    const int z   = blockIdx.z;
    const int m0g = blockIdx.y * 128;
    const int n0g = blockIdx.x * 128;
    const int KT = K >> 4, MFR = Mp >> 4;

    const uint32_t* Wz; const float* Xz; float* Yz;
    const float* maa = nullptr; const float* xb = nullptr; const float* xxb = nullptr;
    if (ACT == 4) {
        int s = z >> 3, b = z & 7;
        Wz = Wp + (size_t)s * KT * MFR * 128;
        Xz = X + (size_t)b * 384 * Nn + (size_t)s * 64 * Nn;
        Yz = Y + (size_t)z * sYz;
        maa = (s==0)?q0:(s==1)?q1:(s==2)?q2:(s==3)?q3:q4;
        xb  = xin + (size_t)b * Cc * Nn;
        xxb = g_xx + (size_t)b * Cc * Nn;
    } else {
        Wz = Wp + (size_t)(z % wmod) * KT * MFR * 128;
        Xz = X + (size_t)z * sXz;
        Yz = Y + (size_t)z * sYz;
    }

    // 136-half row stride = 272 B: 16B-aligned rows (ldmatrix requirement),
    // row base banks spread 4k mod 32 across the 8-row ldmatrix group.
    __shared__ __align__(16) __half Bs[2][16][136];

    const int t = threadIdx.x;
    const int lane = t & 31, wid = t >> 5;
    const int wm = wid >> 2, wn = wid & 3;

    float acc[4][4][4];
    #pragma unroll
    for (int i = 0; i < 4; i++)
        #pragma unroll
        for (int j = 0; j < 4; j++)
            #pragma unroll
            for (int q = 0; q < 4; q++) acc[i][j][q] = 0.f;

    uint4 aR[2][4];
    float4 bR[2];

    // prologue: prefetch kt=0
    #pragma unroll
    for (int mf = 0; mf < 4; mf++) {
        int mfr = (m0g >> 4) + wm * 4 + mf;
        aR[0][mf] = *(const uint4*)&Wz[(((size_t)0 * MFR + mfr) * 32 + lane) * 4];
    }
    #pragma unroll
    for (int q = 0; q < 2; q++) {
        int i = q * 256 + t; int k = i >> 5, n4 = i & 31;
        bR[q] = *(const float4*)&Xz[(size_t)k * Nn + n0g + n4 * 4];
    }

    for (int kt = 0; kt < KT; kt++) {
        int buf = kt & 1;
        // store B tile (fp32 -> fp16)
        #pragma unroll
        for (int q = 0; q < 2; q++) {
            int i = q * 256 + t; int k = i >> 5, n4 = i & 31;
            __half2 h0 = __floats2half2_rn(bR[q].x, bR[q].y);
            __half2 h1 = __floats2half2_rn(bR[q].z, bR[q].w);
            uint32_t* p = (uint32_t*)&Bs[buf][k][n4 * 4];
            p[0] = *(uint32_t*)&h0; p[1] = *(uint32_t*)&h1;
        }
        __syncthreads();
        // prefetch next tile
        if (kt + 1 < KT) {
            #pragma unroll
            for (int mf = 0; mf < 4; mf++) {
                int mfr = (m0g >> 4) + wm * 4 + mf;
                aR[buf ^ 1][mf] =
                    *(const uint4*)&Wz[(((size_t)(kt + 1) * MFR + mfr) * 32 + lane) * 4];
            }
            #pragma unroll
            for (int q = 0; q < 2; q++) {
                int i = q * 256 + t; int k = i >> 5, n4 = i & 31;
                bR[q] = *(const float4*)&Xz[(size_t)((kt + 1) * 16 + k) * Nn + n0g + n4 * 4];
            }
        }
        // compute
        uint32_t base = s2u(&Bs[buf][lane & 15][wn * 32]);
        uint32_t bf[4][2];
        #pragma unroll
        for (int nf = 0; nf < 4; nf++) ldmB(bf[nf][0], bf[nf][1], base + nf * 16);
        #pragma unroll
        for (int mf = 0; mf < 4; mf++)
            #pragma unroll
            for (int nf = 0; nf < 4; nf++)
                mma16(acc[mf][nf], aR[buf][mf], bf[nf][0], bf[nf][1]);
        __syncthreads();
    }

    // epilogue
    #pragma unroll
    for (int mf = 0; mf < 4; mf++) {
        int rr0 = m0g + wm * 64 + mf * 16 + (lane >> 2);
        #pragma unroll
        for (int half = 0; half < 2; half++) {
            int rr = rr0 + half * 8;
            float e  = (ACT == 3) ? extra[rr] : 0.f;
            float mc = (ACT == 4) ? maa[rr]   : 0.f;
            #pragma unroll
            for (int nf = 0; nf < 4; nf++) {
                int nc = n0g + wn * 32 + nf * 8 + (lane & 3) * 2;
                float v0 = acc[mf][nf][half * 2 + 0];
                float v1 = acc[mf][nf][half * 2 + 1];
                size_t off = (size_t)rr * Nn + nc;
                if (ACT == 1) { v0 = tanhf(v0); v1 = tanhf(v1); }
                else if (ACT == 2) { v0 = v0 / (1.f + expf(-v0)); v1 = v1 / (1.f + expf(-v1)); }
                else if (ACT == 3) { v0 = expf(-expf(e + v0)); v1 = expf(-expf(e + v1)); }
                else if (ACT == 4) {
                    float2 xv  = *(const float2*)&xb[off];
                    float2 xxv = *(const float2*)&xxb[off];
                    v0 = fmaf(xxv.x, mc + v0, xv.x);
                    v1 = fmaf(xxv.y, mc + v1, xv.y);
                }
                *(float2*)&Yz[off] = make_float2(v0, v1);
            }
        }
    }
}

// ---------------- K4: pack r,k,dec,v -----------------------------------------------
__global__ void pack_kernel() {
    size_t idx = (size_t)blockIdx.x * 256 + threadIdx.x;
    if (idx >= (size_t)BCN) return;
    int n = (int)(idx & 4095);
    int c = (int)((idx >> 12) % 768);
    int b = (int)(idx / ((size_t)768 * 4096));
    int h = c >> 6, j = c & 63;
    float4 o = make_float4(g_r[idx], g_k[idx], g_dec[idx], g_v[idx]);
    g_rkdv[((size_t)(b * 12 + h) * 4096 + n) * 64 + j] = o;
}

// ---------------- K5: WKV6 sequential scan -----------------------------------------
__global__ void __launch_bounds__(256) scan_kernel(const float* __restrict__ u_in) {
    int bh = blockIdx.x;
    int h = bh % 12, b = bh / 12;
    int t = threadIdx.x;
    int jq = t & 3, i = t >> 2;
    __shared__ float4 buf[2][16][64];
    float S[16], uu[16];
    #pragma unroll
    for (int jj = 0; jj < 16; jj++) { S[jj] = 0.f; uu[jj] = u_in[h * 64 + jq + 4 * jj]; }
    const float4* src = g_rkdv + (size_t)bh * 4096 * 64;
    float* ydst = g_y + (size_t)b * 4096 * 768 + h * 64 + i;
    float4 pre[4];
    #pragma unroll
    for (int q = 0; q < 4; q++) pre[q] = src[t + 256 * q];
    int cur = 0;
    for (int nt = 0; nt < 256; nt++) {
        #pragma unroll
        for (int q = 0; q < 4; q++) ((float4*)buf[cur])[t + 256 * q] = pre[q];
        __syncthreads();
        if (nt + 1 < 256) {
            const float4* nsrc = src + (size_t)(nt + 1) * 1024;
            #pragma unroll
            for (int q = 0; q < 4; q++) pre[q] = nsrc[t + 256 * q];
        }
        #pragma unroll
        for (int s = 0; s < 16; s++) {
            float vi = buf[cur][s][i].w;
            float p = 0.f;
            #pragma unroll
            for (int jj = 0; jj < 16; jj++) {
                float4 f = buf[cur][s][jq + 4 * jj];
                float kv = f.y * vi;
                float tmp = fmaf(uu[jj], kv, S[jj]);
                p = fmaf(f.x, tmp, p);
                S[jj] = fmaf(f.z, S[jj], kv);
            }
            p += __shfl_xor_sync(0xffffffffu, p, 1);
            p += __shfl_xor_sync(0xffffffffu, p, 2);
            if (jq == 0) ydst[(size_t)(nt * 16 + s) * 768] = p;
        }
        __syncthreads();
        cur ^= 1;
    }
}

// ---------------- K6a: RMS over channel dim ----------------------------------------
__global__ void rms_kernel() {
    int row = blockIdx.x * 8 + (threadIdx.x >> 5);
    int lane = threadIdx.x & 31;
    const float* yr = g_y + (size_t)row * 768;
    float s = 0.f;
    #pragma unroll
    for (int q = 0; q < 24; q++) { float v = yr[lane + 32 * q]; s += v * v; }
    #pragma unroll
    for (int off = 16; off; off >>= 1) s += __shfl_xor_sync(0xffffffffu, s, off);
    if (lane == 0) g_rms[row] = rsqrtf(s * (1.f / 768.f) + 1e-6f);
}

// ---------------- K6b: normalize + transpose + gate --------------------------------
__global__ void tgate_kernel(const float* __restrict__ lnw) {
    int b = blockIdx.z;
    int n0 = blockIdx.x * 32, c0 = blockIdx.y * 32;
    __shared__ float tile[32][33];
    int tx = threadIdx.x, ty = threadIdx.y;
    float lw = lnw[c0 + tx];
    for (int r = ty; r < 32; r += 8) {
        int n = n0 + r;
        tile[r][tx] = g_y[((size_t)b * 4096 + n) * 768 + c0 + tx]
                      * g_rms[b * 4096 + n] * lw;
    }
    __syncthreads();
    for (int r = ty; r < 32; r += 8) {
        int c = c0 + r;
        size_t o = ((size_t)b * 768 + c) * 4096 + n0 + tx;
        g_y2[o] = tile[tx][r] * g_gate[o];
    }
}

// ---------------- launch ------------------------------------------------------------
extern "C" void kernel_launch(void* const* d_in, const int* in_sizes, int n_in,
                              void* d_out, int out_size) {
    const float* x        = (const float*)d_in[0];
    const float* maa_x    = (const float*)d_in[1];
    const float* maa_w    = (const float*)d_in[2];
    const float* maa_k    = (const float*)d_in[3];
    const float* maa_v    = (const float*)d_in[4];
    const float* maa_r    = (const float*)d_in[5];
    const float* maa_g    = (const float*)d_in[6];
    const float* maa_w1   = (const float*)d_in[7];
    const float* maa_w2   = (const float*)d_in[8];
    const float* tdecay   = (const float*)d_in[9];
    const float* td_w1    = (const float*)d_in[10];
    const float* td_w2    = (const float*)d_in[11];
    const float* faaaa    = (const float*)d_in[12];
    const float* key_w    = (const float*)d_in[13];
    const float* value_w  = (const float*)d_in[14];
    const float* recept_w = (const float*)d_in[15];
    const float* gate_w   = (const float*)d_in[16];
    const float* out_w    = (const float*)d_in[17];
    const float* ln_x_w   = (const float*)d_in[18];
    float* out = (float*)d_out;

    uint32_t *wh_t, *wh_w2, *wh_r, *wh_k, *wh_v, *wh_g, *wh_o, *wh_td1, *wh_td2;
    cudaGetSymbolAddress((void**)&wh_t,   g_wh_t);
    cudaGetSymbolAddress((void**)&wh_w2,  g_wh_w2);
    cudaGetSymbolAddress((void**)&wh_r,   g_wh_r);
    cudaGetSymbolAddress((void**)&wh_k,   g_wh_k);
    cudaGetSymbolAddress((void**)&wh_v,   g_wh_v);
    cudaGetSymbolAddress((void**)&wh_g,   g_wh_g);
    cudaGetSymbolAddress((void**)&wh_o,   g_wh_o);
    cudaGetSymbolAddress((void**)&wh_td1, g_wh_td1);
    cudaGetSymbolAddress((void**)&wh_td2, g_wh_td2);
    float *p_xxx, *p_t, *p_x5, *p_r, *p_k, *p_v, *p_gate, *p_h, *p_dec, *p_y2;
    cudaGetSymbolAddress((void**)&p_xxx, g_xxx);
    cudaGetSymbolAddress((void**)&p_t,   g_t);
    cudaGetSymbolAddress((void**)&p_x5,  g_x5);
    cudaGetSymbolAddress((void**)&p_r,   g_r);
    cudaGetSymbolAddress((void**)&p_k,   g_k);
    cudaGetSymbolAddress((void**)&p_v,   g_v);
    cudaGetSymbolAddress((void**)&p_gate,g_gate);
    cudaGetSymbolAddress((void**)&p_h,   g_h);
    cudaGetSymbolAddress((void**)&p_dec, g_dec);
    cudaGetSymbolAddress((void**)&p_y2,  g_y2);

    // weight prep (fragment-packed fp16)
    auto PREP = [&](const float* src, uint32_t* dst, int M, int Mp, int K, int tr, int nz) {
        size_t tot = (size_t)nz * (K >> 4) * (Mp >> 4) * 128;
        prep_wh<<<(unsigned)((tot + 255) / 256), 256>>>(src, dst, M, Mp, K, tr, nz);
    };
    PREP(maa_w1,   wh_t,   320, 384, 768, 0, 1);
    PREP(maa_w2,   wh_w2,  768, 768,  64, 1, 5);
    PREP(recept_w, wh_r,   384, 384, 384, 0, 2);
    PREP(key_w,    wh_k,   384, 384, 384, 0, 2);
    PREP(value_w,  wh_v,   384, 384, 384, 0, 2);
    PREP(gate_w,   wh_g,   384, 384, 384, 0, 2);
    PREP(out_w,    wh_o,   384, 384, 384, 0, 2);
    PREP(td_w1,    wh_td1,  64, 128, 768, 0, 1);
    PREP(td_w2,    wh_td2, 768, 768,  64, 0, 1);

    // shift
    shift_kernel<<<(BCN + 255) / 256, 256>>>(x, maa_x);

    #define NUL7 nullptr, nullptr, nullptr, nullptr, nullptr, nullptr, nullptr
    long long sC = (long long)Cc * Nn;      // 768*4096
    long long s384 = (long long)384 * Nn;
    long long s128 = (long long)128 * Nn;

    // t = tanh(maa_w1 @ xxx): Mp=384, K=768, z=B
    gemm_h<1><<<dim3(32, 3, 8), 256>>>(wh_t, p_xxx, p_t, 384, 768, 1,
                                       sC, s384, NUL7);

    // x5 = x + xx*(maa + W2 @ t): Mp=768, K=64, z=s*8+b (40)
    gemm_h<4><<<dim3(32, 6, 40), 256>>>(wh_w2, p_t, p_x5, 768, 64, 5,
                                        0, sC, nullptr, x, maa_w, maa_k, maa_v, maa_r, maa_g);

    // grouped convs: Mp=384, K=384, z = b*2+g (16)
    gemm_h<0><<<dim3(32, 3, 16), 256>>>(wh_r, p_x5 + (size_t)3*BCN, p_r,    384, 384, 2, s384, s384, NUL7);
    gemm_h<0><<<dim3(32, 3, 16), 256>>>(wh_k, p_x5 + (size_t)1*BCN, p_k,    384, 384, 2, s384, s384, NUL7);
    gemm_h<0><<<dim3(32, 3, 16), 256>>>(wh_v, p_x5 + (size_t)2*BCN, p_v,    384, 384, 2, s384, s384, NUL7);
    gemm_h<2><<<dim3(32, 3, 16), 256>>>(wh_g, p_x5 + (size_t)4*BCN, p_gate, 384, 384, 2, s384, s384, NUL7);

    // decay MLP: h = tanh(td_w1 @ xw)  (Mp=128 padded);  dec = exp(-exp(td + td_w2 @ h))
    gemm_h<1><<<dim3(32, 1, 8), 256>>>(wh_td1, p_x5, p_h, 128, 768, 1, sC, s128, NUL7);
    gemm_h<3><<<dim3(32, 6, 8), 256>>>(wh_td2, p_h, p_dec, 768, 64, 1, s128, sC,
                                       tdecay, nullptr, nullptr, nullptr, nullptr, nullptr, nullptr);

    // pack + scan
    pack_kernel<<<(BCN + 255) / 256, 256>>>();
    scan_kernel<<<96, 256>>>(faaaa);

    // rmsnorm + transpose + gate
    rms_kernel<<<TOK / 8, 256>>>();
    tgate_kernel<<<dim3(128, 24, 8), dim3(32, 8)>>>(ln_x_w);

    // final grouped conv -> out
    gemm_h<0><<<dim3(32, 3, 16), 256>>>(wh_o, p_y2, out, 384, 384, 2, s384, s384, NUL7);
}

// round 10
// speedup vs baseline: 1.6400x; 1.0518x over previous
#include <cuda_runtime.h>
#include <cuda_fp16.h>
#include <cstdint>
#include <cstddef>

#define Bb 8
#define Cc 768
#define Nn 4096
#define TOK (Bb*Nn)
#define BCN (Bb*Cc*Nn)   // 25165824

// ---------------- scratch (static device globals) ---------------------------------
__device__ __align__(16) float g_xx [BCN];
__device__ __align__(16) float g_xxx[BCN];
__device__ __align__(16) float g_t  [Bb*384*Nn];
__device__ __align__(16) __half g_x5h [5u*(size_t)BCN];   // fp16: s slices 0=xw 1=xk 2=xv 3=xr 4=xg
__device__ __align__(16) __half g_gateh[BCN];             // channel-major (B,C,N)
__device__ __align__(16) float g_h  [(size_t)Bb*128*Nn];  // decay hidden, padded M=128
__device__ float4 g_rkdv[(size_t)Bb*12*Nn*64];            // (r,k,dec,v) per (bh,n,j)
__device__ __align__(16) float g_y  [BCN];                // scan out, token-major (B,N,C)
__device__ __align__(16) __half g_y2h[BCN];               // normalized+gated, channel-major
// fp16 fragment-packed weights: [z][kt][mfr][lane][4] uint32 (half2)
__device__ __align__(16) uint32_t g_wh_t  [48*24*128];
__device__ __align__(16) uint32_t g_wh_w2 [5*4*48*128];
__device__ __align__(16) uint32_t g_wh_r  [2*24*24*128];
__device__ __align__(16) uint32_t g_wh_k  [2*24*24*128];
__device__ __align__(16) uint32_t g_wh_v  [2*24*24*128];
__device__ __align__(16) uint32_t g_wh_g  [2*24*24*128];
__device__ __align__(16) uint32_t g_wh_o  [2*24*24*128];
__device__ __align__(16) uint32_t g_wh_td1[48*8*128];
__device__ __align__(16) uint32_t g_wh_td2[4*48*128];

// ---------------- asm helpers ------------------------------------------------------
__device__ __forceinline__ uint32_t s2u(const void* p) {
    uint32_t a;
    asm("{ .reg .u64 t; cvta.to.shared.u64 t, %1; cvt.u32.u64 %0, t; }" : "=r"(a) : "l"(p));
    return a;
}
__device__ __forceinline__ void mma16(float* d, const uint4& a, uint32_t b0, uint32_t b1) {
    asm volatile("mma.sync.aligned.m16n8k16.row.col.f32.f16.f16.f32 "
        "{%0,%1,%2,%3}, {%4,%5,%6,%7}, {%8,%9}, {%0,%1,%2,%3};"
        : "+f"(d[0]), "+f"(d[1]), "+f"(d[2]), "+f"(d[3])
        : "r"(a.x), "r"(a.y), "r"(a.z), "r"(a.w), "r"(b0), "r"(b1));
}
__device__ __forceinline__ void ldmB(uint32_t& b0, uint32_t& b1, uint32_t addr) {
    asm volatile("ldmatrix.sync.aligned.m8n8.x2.trans.shared.b16 {%0,%1}, [%2];"
        : "=r"(b0), "=r"(b1) : "r"(addr));
}

// ---------------- weight prep: fragment-packed fp16 --------------------------------
__global__ void prep_wh(const float* __restrict__ src, uint32_t* __restrict__ dst,
                        int M, int Mp, int K, int trans, int nz) {
    size_t idx = (size_t)blockIdx.x * 256 + threadIdx.x;
    int KT = K >> 4, MFR = Mp >> 4;
    size_t per_z = (size_t)KT * MFR * 128;
    if (idx >= per_z * nz) return;
    int z = (int)(idx / per_z);
    size_t rem = idx - (size_t)z * per_z;
    int kt  = (int)(rem / (MFR * 128));
    int r2  = (int)(rem % (MFR * 128));
    int mfr = r2 >> 7;
    int li  = r2 & 127;
    int lane = li >> 2, r = li & 3;
    int m = mfr * 16 + (lane >> 2) + ((r & 1) << 3);
    int k = kt * 16 + (lane & 3) * 2 + ((r >> 1) << 3);
    float f0 = 0.f, f1 = 0.f;
    if (m < M) {
        const float* sz = src + (size_t)z * M * K;
        if (trans) { f0 = sz[(size_t)k * M + m]; f1 = sz[(size_t)(k + 1) * M + m]; }
        else       { f0 = sz[(size_t)m * K + k]; f1 = sz[(size_t)m * K + k + 1]; }
    }
    __half2 h = __floats2half2_rn(f0, f1);
    dst[idx] = *(uint32_t*)&h;
}

// ---------------- K1: q_shift + xx + xxx -------------------------------------------
__global__ void shift_kernel(const float* __restrict__ x, const float* __restrict__ maa_x) {
    size_t idx = (size_t)blockIdx.x * 256 + threadIdx.x;
    if (idx >= (size_t)BCN) return;
    int n = (int)(idx & (Nn - 1));
    int c = (int)((idx >> 12) % Cc);
    int w = n & 63, hh = n >> 6;
    float xv = x[idx], s;
    int mode = c / 192;
    if (mode == 0)      s = (w  > 0 ) ? x[idx - 1 ] : 0.f;
    else if (mode == 1) s = (w  < 63) ? x[idx + 1 ] : 0.f;
    else if (mode == 2) s = (hh > 0 ) ? x[idx - 64] : 0.f;
    else                s = (hh < 63) ? x[idx + 64] : 0.f;
    float d = s - xv;
    g_xx[idx]  = d;
    g_xxx[idx] = fmaf(d, maa_x[c], xv);
}

// ---------------- fp16 tensor-core GEMM --------------------------------------------
// 256 thr, 8 warps, block 128(M)x128(N), warp 64x32.
// ACT: 0 none, 1 tanh, 2 silu, 3 decay exp(-exp(extra[m]+v)), 4 mix fuse (z=b*5+s)
// IN:  0 fp32 X, 1 fp16 X.   OUT: 0 fp32, 1 fp16 (half2), 2 scatter into g_rkdv[comp]
template<int ACT, int IN, int OUT>
__global__ void __launch_bounds__(256) gemm_h(
    const uint32_t* __restrict__ Wp, const void* __restrict__ Xv,
    void* __restrict__ Yv, int Mp, int K, int wmod,
    long long sXz, long long sYz, int zdiv, int comp,
    const float* __restrict__ extra, const float* __restrict__ xin,
    const float* __restrict__ q0, const float* __restrict__ q1,
    const float* __restrict__ q2, const float* __restrict__ q3,
    const float* __restrict__ q4)
{
    const int z   = blockIdx.z;
    const int m0g = blockIdx.y * 128;
    const int n0g = blockIdx.x * 128;
    const int KT = K >> 4, MFR = Mp >> 4;

    const uint32_t* Wz;
    const float* Xzf = nullptr; const __half* Xzh = nullptr;
    float* Yzf = nullptr; __half* Yzh = nullptr;
    const float* maa = nullptr; const float* xb = nullptr; const float* xxb = nullptr;
    if (ACT == 4) {
        int s = z % 5, b = z / 5;
        Wz = Wp + (size_t)s * KT * MFR * 128;
        Xzf = (const float*)Xv + (size_t)b * 384 * Nn + (size_t)s * 64 * Nn;
        Yzh = (__half*)Yv + (size_t)(s * 8 + b) * sYz;
        maa = (s==0)?q0:(s==1)?q1:(s==2)?q2:(s==3)?q3:q4;
        xb  = xin + (size_t)b * Cc * Nn;
        xxb = g_xx + (size_t)b * Cc * Nn;
    } else {
        Wz = Wp + (size_t)(z % wmod) * KT * MFR * 128;
        if (IN == 0) Xzf = (const float*)Xv + (size_t)z * sXz;
        else         Xzh = (const __half*)Xv + (size_t)z * sXz;
        if (OUT == 0)      Yzf = (float*)Yv + (size_t)z * sYz;
        else if (OUT == 1) Yzh = (__half*)Yv + (size_t)z * sYz;
    }

    __shared__ __align__(16) __half Bs[2][16][136];   // 272B rows: 16B-aligned

    const int t = threadIdx.x;
    const int lane = t & 31, wid = t >> 5;
    const int wm = wid >> 2, wn = wid & 3;

    float acc[4][4][4];
    #pragma unroll
    for (int i = 0; i < 4; i++)
        #pragma unroll
        for (int j = 0; j < 4; j++)
            #pragma unroll
            for (int q = 0; q < 4; q++) acc[i][j][q] = 0.f;

    uint4 aR[2][4];
    float4 bRf[2];
    uint4  bRh;

    // prologue: prefetch kt=0
    #pragma unroll
    for (int mf = 0; mf < 4; mf++) {
        int mfr = (m0g >> 4) + wm * 4 + mf;
        aR[0][mf] = *(const uint4*)&Wz[(((size_t)0 * MFR + mfr) * 32 + lane) * 4];
    }
    if (IN == 0) {
        #pragma unroll
        for (int q = 0; q < 2; q++) {
            int i = q * 256 + t; int k = i >> 5, n4 = i & 31;
            bRf[q] = *(const float4*)&Xzf[(size_t)k * Nn + n0g + n4 * 4];
        }
    } else {
        int k = t >> 4, c8 = (t & 15) * 8;
        bRh = *(const uint4*)&Xzh[(size_t)k * Nn + n0g + c8];
    }

    for (int kt = 0; kt < KT; kt++) {
        int buf = kt & 1;
        // store B tile to smem
        if (IN == 0) {
            #pragma unroll
            for (int q = 0; q < 2; q++) {
                int i = q * 256 + t; int k = i >> 5, n4 = i & 31;
                __half2 h0 = __floats2half2_rn(bRf[q].x, bRf[q].y);
                __half2 h1 = __floats2half2_rn(bRf[q].z, bRf[q].w);
                uint32_t* p = (uint32_t*)&Bs[buf][k][n4 * 4];
                p[0] = *(uint32_t*)&h0; p[1] = *(uint32_t*)&h1;
            }
        } else {
            int k = t >> 4, c8 = (t & 15) * 8;
            *(uint4*)&Bs[buf][k][c8] = bRh;
        }
        __syncthreads();
        // prefetch next tile
        if (kt + 1 < KT) {
            #pragma unroll
            for (int mf = 0; mf < 4; mf++) {
                int mfr = (m0g >> 4) + wm * 4 + mf;
                aR[buf ^ 1][mf] =
                    *(const uint4*)&Wz[(((size_t)(kt + 1) * MFR + mfr) * 32 + lane) * 4];
            }
            if (IN == 0) {
                #pragma unroll
                for (int q = 0; q < 2; q++) {
                    int i = q * 256 + t; int k = i >> 5, n4 = i & 31;
                    bRf[q] = *(const float4*)&Xzf[(size_t)((kt + 1) * 16 + k) * Nn + n0g + n4 * 4];
                }
            } else {
                int k = t >> 4, c8 = (t & 15) * 8;
                bRh = *(const uint4*)&Xzh[(size_t)((kt + 1) * 16 + k) * Nn + n0g + c8];
            }
        }
        // compute
        uint32_t base = s2u(&Bs[buf][lane & 15][wn * 32]);
        uint32_t bf[4][2];
        #pragma unroll
        for (int nf = 0; nf < 4; nf++) ldmB(bf[nf][0], bf[nf][1], base + nf * 16);
        #pragma unroll
        for (int mf = 0; mf < 4; mf++)
            #pragma unroll
            for (int nf = 0; nf < 4; nf++)
                mma16(acc[mf][nf], aR[buf][mf], bf[nf][0], bf[nf][1]);
        __syncthreads();
    }

    // epilogue
    #pragma unroll
    for (int mf = 0; mf < 4; mf++) {
        int rr0 = m0g + wm * 64 + mf * 16 + (lane >> 2);
        #pragma unroll
        for (int hf = 0; hf < 2; hf++) {
            int rr = rr0 + hf * 8;
            float e  = (ACT == 3) ? extra[rr] : 0.f;
            float mc = (ACT == 4) ? maa[rr]   : 0.f;
            #pragma unroll
            for (int nf = 0; nf < 4; nf++) {
                int nc = n0g + wn * 32 + nf * 8 + (lane & 3) * 2;
                float v0 = acc[mf][nf][hf * 2 + 0];
                float v1 = acc[mf][nf][hf * 2 + 1];
                size_t off = (size_t)rr * Nn + nc;
                if (ACT == 1) { v0 = tanhf(v0); v1 = tanhf(v1); }
                else if (ACT == 2) { v0 = v0 / (1.f + expf(-v0)); v1 = v1 / (1.f + expf(-v1)); }
                else if (ACT == 3) { v0 = expf(-expf(e + v0)); v1 = expf(-expf(e + v1)); }
                else if (ACT == 4) {
                    float2 xv  = *(const float2*)&xb[off];
                    float2 xxv = *(const float2*)&xxb[off];
                    v0 = fmaf(xxv.x, mc + v0, xv.x);
                    v1 = fmaf(xxv.y, mc + v1, xv.y);
                }
                if (OUT == 0) {
                    *(float2*)&Yzf[off] = make_float2(v0, v1);
                } else if (OUT == 1) {
                    __half2 h = __floats2half2_rn(v0, v1);
                    *(__half2*)&Yzh[off] = h;
                } else {
                    int b_ = z / zdiv;
                    int c  = (z % zdiv) * 384 + rr;
                    float* rk = (float*)g_rkdv;
                    size_t base2 = ((((size_t)(b_ * 12 + (c >> 6)) * 4096 + nc) * 64)
                                    + (c & 63)) * 4 + comp;
                    rk[base2] = v0;
                    rk[base2 + 256] = v1;   // +1 token = +64 float4
                }
            }
        }
    }
}

// ---------------- K5: WKV6 sequential scan (512 thr, 8 j-groups) -------------------
__global__ void __launch_bounds__(512) scan_kernel(const float* __restrict__ u_in) {
    int bh = blockIdx.x;
    int h = bh % 12, b = bh / 12;
    int t = threadIdx.x;
    int jq = t & 7, i = t >> 3;          // i in 0..63
    __shared__ float4 buf[2][16][64];
    float S[8], uu[8];
    #pragma unroll
    for (int jj = 0; jj < 8; jj++) { S[jj] = 0.f; uu[jj] = u_in[h * 64 + jq + 8 * jj]; }
    const float4* src = g_rkdv + (size_t)bh * 4096 * 64;
    float* ydst = g_y + (size_t)b * 4096 * 768 + h * 64 + i;
    float4 pre[2];
    #pragma unroll
    for (int q = 0; q < 2; q++) pre[q] = src[t + 512 * q];
    int cur = 0;
    for (int nt = 0; nt < 256; nt++) {
        #pragma unroll
        for (int q = 0; q < 2; q++) ((float4*)buf[cur])[t + 512 * q] = pre[q];
        __syncthreads();
        if (nt + 1 < 256) {
            const float4* nsrc = src + (size_t)(nt + 1) * 1024;
            #pragma unroll
            for (int q = 0; q < 2; q++) pre[q] = nsrc[t + 512 * q];
        }
        #pragma unroll
        for (int s = 0; s < 16; s++) {
            float vi = buf[cur][s][i].w;
            float p = 0.f;
            #pragma unroll
            for (int jj = 0; jj < 8; jj++) {
                float4 f = buf[cur][s][jq + 8 * jj];
                float kv = f.y * vi;
                float tmp = fmaf(uu[jj], kv, S[jj]);
                p = fmaf(f.x, tmp, p);
                S[jj] = fmaf(f.z, S[jj], kv);
            }
            p += __shfl_xor_sync(0xffffffffu, p, 1);
            p += __shfl_xor_sync(0xffffffffu, p, 2);
            p += __shfl_xor_sync(0xffffffffu, p, 4);
            if (jq == 0) ydst[(size_t)(nt * 16 + s) * 768] = p;
        }
        __syncthreads();
        cur ^= 1;
    }
}

// ---------------- K6: fused RMS + gate + transpose, fp16 channel-major out ---------
// one block = 32 tokens; y staged in dynamic smem [32][769] floats.
__global__ void __launch_bounds__(256) rmstgate_kernel(const float* __restrict__ lnw) {
    extern __shared__ float sy[];                 // [32][769]
    __shared__ float rmsv[32];
    const int t = threadIdx.x;
    const int tok0 = blockIdx.x * 32;
    const int b = tok0 >> 12, n0 = tok0 & 4095;
    const float* ybase = g_y + (size_t)tok0 * 768;

    // stage y: 32 x 768 floats = 6144 float4
    #pragma unroll
    for (int it = 0; it < 24; it++) {
        int i = it * 256 + t;
        int tr = i / 192, c4 = i % 192;
        float4 v = *(const float4*)&ybase[(size_t)tr * 768 + c4 * 4];
        float* row = &sy[tr * 769];
        row[c4 * 4 + 0] = v.x; row[c4 * 4 + 1] = v.y;
        row[c4 * 4 + 2] = v.z; row[c4 * 4 + 3] = v.w;
    }
    __syncthreads();

    // rms per token: warp w handles tokens 4w..4w+3
    {
        int w = t >> 5, lane = t & 31;
        #pragma unroll
        for (int q = 0; q < 4; q++) {
            int tr = w * 4 + q;
            const float* row = &sy[tr * 769];
            float s = 0.f;
            #pragma unroll
            for (int j = 0; j < 24; j++) { float v = row[lane + 32 * j]; s += v * v; }
            #pragma unroll
            for (int off = 16; off; off >>= 1) s += __shfl_xor_sync(0xffffffffu, s, off);
            if (lane == 0) rmsv[tr] = rsqrtf(s * (1.f / 768.f) + 1e-6f);
        }
    }
    __syncthreads();

    // write channel-major fp16: 768 c x 32 tokens
    #pragma unroll 4
    for (int it = 0; it < 96; it++) {
        int i = it * 256 + t;
        int c = i >> 5, tr = i & 31;
        float val = sy[c + tr * 769];              // wait: need sy[tr][c]
        val = sy[tr * 769 + c];
        size_t go = ((size_t)(b * 768 + c)) * 4096 + n0 + tr;
        float g = __half2float(g_gateh[go]);
        g_y2h[go] = __float2half(val * rmsv[tr] * lnw[c] * g);
    }
}

// ---------------- launch ------------------------------------------------------------
extern "C" void kernel_launch(void* const* d_in, const int* in_sizes, int n_in,
                              void* d_out, int out_size) {
    const float* x        = (const float*)d_in[0];
    const float* maa_x    = (const float*)d_in[1];
    const float* maa_w    = (const float*)d_in[2];
    const float* maa_k    = (const float*)d_in[3];
    const float* maa_v    = (const float*)d_in[4];
    const float* maa_r    = (const float*)d_in[5];
    const float* maa_g    = (const float*)d_in[6];
    const float* maa_w1   = (const float*)d_in[7];
    const float* maa_w2   = (const float*)d_in[8];
    const float* tdecay   = (const float*)d_in[9];
    const float* td_w1    = (const float*)d_in[10];
    const float* td_w2    = (const float*)d_in[11];
    const float* faaaa    = (const float*)d_in[12];
    const float* key_w    = (const float*)d_in[13];
    const float* value_w  = (const float*)d_in[14];
    const float* recept_w = (const float*)d_in[15];
    const float* gate_w   = (const float*)d_in[16];
    const float* out_w    = (const float*)d_in[17];
    const float* ln_x_w   = (const float*)d_in[18];
    float* out = (float*)d_out;

    uint32_t *wh_t, *wh_w2, *wh_r, *wh_k, *wh_v, *wh_g, *wh_o, *wh_td1, *wh_td2;
    cudaGetSymbolAddress((void**)&wh_t,   g_wh_t);
    cudaGetSymbolAddress((void**)&wh_w2,  g_wh_w2);
    cudaGetSymbolAddress((void**)&wh_r,   g_wh_r);
    cudaGetSymbolAddress((void**)&wh_k,   g_wh_k);
    cudaGetSymbolAddress((void**)&wh_v,   g_wh_v);
    cudaGetSymbolAddress((void**)&wh_g,   g_wh_g);
    cudaGetSymbolAddress((void**)&wh_o,   g_wh_o);
    cudaGetSymbolAddress((void**)&wh_td1, g_wh_td1);
    cudaGetSymbolAddress((void**)&wh_td2, g_wh_td2);
    float *p_xxx, *p_t, *p_h;
    __half *p_x5h, *p_gateh, *p_y2h;
    cudaGetSymbolAddress((void**)&p_xxx,  g_xxx);
    cudaGetSymbolAddress((void**)&p_t,    g_t);
    cudaGetSymbolAddress((void**)&p_h,    g_h);
    cudaGetSymbolAddress((void**)&p_x5h,  g_x5h);
    cudaGetSymbolAddress((void**)&p_gateh,g_gateh);
    cudaGetSymbolAddress((void**)&p_y2h,  g_y2h);

    // weight prep
    auto PREP = [&](const float* src, uint32_t* dst, int M, int Mp, int K, int tr, int nz) {
        size_t tot = (size_t)nz * (K >> 4) * (Mp >> 4) * 128;
        prep_wh<<<(unsigned)((tot + 255) / 256), 256>>>(src, dst, M, Mp, K, tr, nz);
    };
    PREP(maa_w1,   wh_t,   320, 384, 768, 0, 1);
    PREP(maa_w2,   wh_w2,  768, 768,  64, 1, 5);
    PREP(recept_w, wh_r,   384, 384, 384, 0, 2);
    PREP(key_w,    wh_k,   384, 384, 384, 0, 2);
    PREP(value_w,  wh_v,   384, 384, 384, 0, 2);
    PREP(gate_w,   wh_g,   384, 384, 384, 0, 2);
    PREP(out_w,    wh_o,   384, 384, 384, 0, 2);
    PREP(td_w1,    wh_td1,  64, 128, 768, 0, 1);
    PREP(td_w2,    wh_td2, 768, 768,  64, 0, 1);

    shift_kernel<<<(BCN + 255) / 256, 256>>>(x, maa_x);

    #define NUL5 nullptr, nullptr, nullptr, nullptr, nullptr
    long long sC   = (long long)Cc * Nn;
    long long s384 = (long long)384 * Nn;
    long long s128 = (long long)128 * Nn;

    // t = tanh(maa_w1 @ xxx): Mp=384, K=768, z=B, fp32 in, fp32 out
    gemm_h<1,0,0><<<dim3(32, 3, 8), 256>>>(wh_t, p_xxx, p_t, 384, 768, 1,
                                           sC, s384, 1, 0, nullptr, nullptr, NUL5);

    // x5h = x + xx*(maa + W2 @ t): z=b*5+s (40), fp32 in (t), fp16 out
    gemm_h<4,0,1><<<dim3(32, 6, 40), 256>>>(wh_w2, p_t, p_x5h, 768, 64, 5,
                                            0, sC, 1, 0, nullptr, x,
                                            maa_w, maa_k, maa_v, maa_r, maa_g);

    // grouped convs (fp16 in), r/k/v scatter into rkdv comps 0/1/3
    gemm_h<0,1,2><<<dim3(32, 3, 16), 256>>>(wh_r, p_x5h + (size_t)3*BCN, nullptr, 384, 384, 2,
                                            s384, 0, 2, 0, nullptr, nullptr, NUL5);
    gemm_h<0,1,2><<<dim3(32, 3, 16), 256>>>(wh_k, p_x5h + (size_t)1*BCN, nullptr, 384, 384, 2,
                                            s384, 0, 2, 1, nullptr, nullptr, NUL5);
    gemm_h<0,1,2><<<dim3(32, 3, 16), 256>>>(wh_v, p_x5h + (size_t)2*BCN, nullptr, 384, 384, 2,
                                            s384, 0, 2, 3, nullptr, nullptr, NUL5);
    // gate conv: fp16 in, fp16 out (channel-major)
    gemm_h<2,1,1><<<dim3(32, 3, 16), 256>>>(wh_g, p_x5h + (size_t)4*BCN, p_gateh, 384, 384, 2,
                                            s384, s384, 1, 0, nullptr, nullptr, NUL5);

    // decay MLP: h = tanh(td_w1 @ xw) fp16 in fp32 out; dec scatter comp 2
    gemm_h<1,1,0><<<dim3(32, 1, 8), 256>>>(wh_td1, p_x5h, p_h, 128, 768, 1,
                                           sC, s128, 1, 0, nullptr, nullptr, NUL5);
    gemm_h<3,0,2><<<dim3(32, 6, 8), 256>>>(wh_td2, p_h, nullptr, 768, 64, 1,
                                           s128, 0, 1, 2, tdecay, nullptr, NUL5);

    // scan
    scan_kernel<<<96, 512>>>(faaaa);

    // fused rms + gate + transpose -> y2h (channel-major fp16)
    cudaFuncSetAttribute(rmstgate_kernel, cudaFuncAttributeMaxDynamicSharedMemorySize,
                         32 * 769 * 4);
    rmstgate_kernel<<<TOK / 32, 256, 32 * 769 * 4>>>(ln_x_w);

    // final grouped conv (fp16 in) -> out (fp32 channel-major)
    gemm_h<0,1,0><<<dim3(32, 3, 16), 256>>>(wh_o, p_y2h, out, 384, 384, 2,
                                            s384, s384, 1, 0, nullptr, nullptr, NUL5);
}

// round 11
// speedup vs baseline: 1.7972x; 1.0958x over previous
#include <cuda_runtime.h>
#include <cuda_fp16.h>
#include <cstdint>
#include <cstddef>

#define Bb 8
#define Cc 768
#define Nn 4096
#define TOK (Bb*Nn)
#define BCN (Bb*Cc*Nn)   // 25165824

// ---------------- scratch (static device globals) ---------------------------------
__device__ __align__(16) float  g_xx  [BCN];              // channel-major (B,C,N)
__device__ __align__(16) __half g_xxxh[BCN];              // fp16 (mma operand only)
__device__ __align__(16) __half g_th  [Bb*384*Nn];        // t, fp16
__device__ __align__(16) __half g_x5h [5u*(size_t)BCN];   // s: 0=xw 1=xk 2=xv 3=xr 4=xg
__device__ __align__(16) __half g_gateh[BCN];
__device__ __align__(16) __half g_hh  [(size_t)Bb*128*Nn];// decay hidden fp16 (padded)
__device__ __align__(16) float  g_r   [BCN];              // conv outputs fp32 (b,c,n)
__device__ __align__(16) float  g_k   [BCN];
__device__ __align__(16) float  g_v   [BCN];
__device__ __align__(16) float  g_dec [BCN];
__device__ __align__(16) float  g_y   [BCN];              // scan out (b,n,c)
__device__ __align__(16) __half g_y2h [BCN];              // normalized+gated (b,c,n)
// fp16 fragment-packed weights: [z][kt][mfr][lane][4] uint32 (half2)
__device__ __align__(16) uint32_t g_wh_t  [48*24*128];
__device__ __align__(16) uint32_t g_wh_w2 [5*4*48*128];
__device__ __align__(16) uint32_t g_wh_r  [2*24*24*128];
__device__ __align__(16) uint32_t g_wh_k  [2*24*24*128];
__device__ __align__(16) uint32_t g_wh_v  [2*24*24*128];
__device__ __align__(16) uint32_t g_wh_g  [2*24*24*128];
__device__ __align__(16) uint32_t g_wh_o  [2*24*24*128];
__device__ __align__(16) uint32_t g_wh_td1[48*8*128];
__device__ __align__(16) uint32_t g_wh_td2[4*48*128];

// ---------------- asm helpers ------------------------------------------------------
__device__ __forceinline__ uint32_t s2u(const void* p) {
    uint32_t a;
    asm("{ .reg .u64 t; cvta.to.shared.u64 t, %1; cvt.u32.u64 %0, t; }" : "=r"(a) : "l"(p));
    return a;
}
__device__ __forceinline__ void mma16(float* d, const uint4& a, uint32_t b0, uint32_t b1) {
    asm volatile("mma.sync.aligned.m16n8k16.row.col.f32.f16.f16.f32 "
        "{%0,%1,%2,%3}, {%4,%5,%6,%7}, {%8,%9}, {%0,%1,%2,%3};"
        : "+f"(d[0]), "+f"(d[1]), "+f"(d[2]), "+f"(d[3])
        : "r"(a.x), "r"(a.y), "r"(a.z), "r"(a.w), "r"(b0), "r"(b1));
}
__device__ __forceinline__ void ldmB(uint32_t& b0, uint32_t& b1, uint32_t addr) {
    asm volatile("ldmatrix.sync.aligned.m8n8.x2.trans.shared.b16 {%0,%1}, [%2];"
        : "=r"(b0), "=r"(b1) : "r"(addr));
}

// ---------------- weight prep: fragment-packed fp16 --------------------------------
__global__ void prep_wh(const float* __restrict__ src, uint32_t* __restrict__ dst,
                        int M, int Mp, int K, int trans, int nz) {
    size_t idx = (size_t)blockIdx.x * 256 + threadIdx.x;
    int KT = K >> 4, MFR = Mp >> 4;
    size_t per_z = (size_t)KT * MFR * 128;
    if (idx >= per_z * nz) return;
    int z = (int)(idx / per_z);
    size_t rem = idx - (size_t)z * per_z;
    int kt  = (int)(rem / (MFR * 128));
    int r2  = (int)(rem % (MFR * 128));
    int mfr = r2 >> 7;
    int li  = r2 & 127;
    int lane = li >> 2, r = li & 3;
    int m = mfr * 16 + (lane >> 2) + ((r & 1) << 3);
    int k = kt * 16 + (lane & 3) * 2 + ((r >> 1) << 3);
    float f0 = 0.f, f1 = 0.f;
    if (m < M) {
        const float* sz = src + (size_t)z * M * K;
        if (trans) { f0 = sz[(size_t)k * M + m]; f1 = sz[(size_t)(k + 1) * M + m]; }
        else       { f0 = sz[(size_t)m * K + k]; f1 = sz[(size_t)m * K + k + 1]; }
    }
    __half2 h = __floats2half2_rn(f0, f1);
    dst[idx] = *(uint32_t*)&h;
}

// ---------------- K1: q_shift + xx(fp32) + xxx(fp16) -------------------------------
__global__ void shift_kernel(const float* __restrict__ x, const float* __restrict__ maa_x) {
    size_t idx = (size_t)blockIdx.x * 256 + threadIdx.x;
    if (idx >= (size_t)BCN) return;
    int n = (int)(idx & (Nn - 1));
    int c = (int)((idx >> 12) % Cc);
    int w = n & 63, hh = n >> 6;
    float xv = x[idx], s;
    int mode = c / 192;
    if (mode == 0)      s = (w  > 0 ) ? x[idx - 1 ] : 0.f;
    else if (mode == 1) s = (w  < 63) ? x[idx + 1 ] : 0.f;
    else if (mode == 2) s = (hh > 0 ) ? x[idx - 64] : 0.f;
    else                s = (hh < 63) ? x[idx + 64] : 0.f;
    float d = s - xv;
    g_xx[idx]   = d;
    g_xxxh[idx] = __float2half(fmaf(d, maa_x[c], xv));
}

// ---------------- fp16 tensor-core GEMM --------------------------------------------
// 256 thr, 8 warps, block 128(M)x128(N), warp 64x32. X is fp16 everywhere now.
// ACT: 0 none, 1 tanh, 2 silu, 3 decay exp(-exp(extra[m]+v)), 4 mix fuse (z=b*5+s)
// OUT: 0 fp32, 1 fp16
template<int ACT, int OUT>
__global__ void __launch_bounds__(256) gemm_h(
    const uint32_t* __restrict__ Wp, const __half* __restrict__ X,
    void* __restrict__ Yv, int Mp, int K, int wmod,
    long long sXz, long long sYz,
    const float* __restrict__ extra, const float* __restrict__ xin,
    const float* __restrict__ q0, const float* __restrict__ q1,
    const float* __restrict__ q2, const float* __restrict__ q3,
    const float* __restrict__ q4)
{
    const int z   = blockIdx.z;
    const int m0g = blockIdx.y * 128;
    const int n0g = blockIdx.x * 128;
    const int KT = K >> 4, MFR = Mp >> 4;

    const uint32_t* Wz;
    const __half* Xz;
    float* Yzf = nullptr; __half* Yzh = nullptr;
    const float* maa = nullptr; const float* xb = nullptr; const float* xxb = nullptr;
    if (ACT == 4) {
        int s = z % 5, b = z / 5;
        Wz = Wp + (size_t)s * KT * MFR * 128;
        Xz = X + (size_t)b * 384 * Nn + (size_t)s * 64 * Nn;
        Yzh = (__half*)Yv + (size_t)(s * 8 + b) * sYz;
        maa = (s==0)?q0:(s==1)?q1:(s==2)?q2:(s==3)?q3:q4;
        xb  = xin + (size_t)b * Cc * Nn;
        xxb = g_xx + (size_t)b * Cc * Nn;
    } else {
        Wz = Wp + (size_t)(z % wmod) * KT * MFR * 128;
        Xz = X + (size_t)z * sXz;
        if (OUT == 0) Yzf = (float*)Yv + (size_t)z * sYz;
        else          Yzh = (__half*)Yv + (size_t)z * sYz;
    }

    __shared__ __align__(16) __half Bs[2][16][136];   // 272B rows: 16B-aligned

    const int t = threadIdx.x;
    const int lane = t & 31, wid = t >> 5;
    const int wm = wid >> 2, wn = wid & 3;

    float acc[4][4][4];
    #pragma unroll
    for (int i = 0; i < 4; i++)
        #pragma unroll
        for (int jx = 0; jx < 4; jx++)
            #pragma unroll
            for (int q = 0; q < 4; q++) acc[i][jx][q] = 0.f;

    uint4 aR[2][4];
    uint4 bRh;

    #pragma unroll
    for (int mf = 0; mf < 4; mf++) {
        int mfr = (m0g >> 4) + wm * 4 + mf;
        aR[0][mf] = *(const uint4*)&Wz[(((size_t)0 * MFR + mfr) * 32 + lane) * 4];
    }
    {
        int k = t >> 4, c8 = (t & 15) * 8;
        bRh = *(const uint4*)&Xz[(size_t)k * Nn + n0g + c8];
    }

    for (int kt = 0; kt < KT; kt++) {
        int buf = kt & 1;
        {
            int k = t >> 4, c8 = (t & 15) * 8;
            *(uint4*)&Bs[buf][k][c8] = bRh;
        }
        __syncthreads();
        if (kt + 1 < KT) {
            #pragma unroll
            for (int mf = 0; mf < 4; mf++) {
                int mfr = (m0g >> 4) + wm * 4 + mf;
                aR[buf ^ 1][mf] =
                    *(const uint4*)&Wz[(((size_t)(kt + 1) * MFR + mfr) * 32 + lane) * 4];
            }
            int k = t >> 4, c8 = (t & 15) * 8;
            bRh = *(const uint4*)&Xz[(size_t)((kt + 1) * 16 + k) * Nn + n0g + c8];
        }
        uint32_t base = s2u(&Bs[buf][lane & 15][wn * 32]);
        uint32_t bf[4][2];
        #pragma unroll
        for (int nf = 0; nf < 4; nf++) ldmB(bf[nf][0], bf[nf][1], base + nf * 16);
        #pragma unroll
        for (int mf = 0; mf < 4; mf++)
            #pragma unroll
            for (int nf = 0; nf < 4; nf++)
                mma16(acc[mf][nf], aR[buf][mf], bf[nf][0], bf[nf][1]);
        __syncthreads();
    }

    // epilogue
    #pragma unroll
    for (int mf = 0; mf < 4; mf++) {
        int rr0 = m0g + wm * 64 + mf * 16 + (lane >> 2);
        #pragma unroll
        for (int hf = 0; hf < 2; hf++) {
            int rr = rr0 + hf * 8;
            float e  = (ACT == 3) ? extra[rr] : 0.f;
            float mc = (ACT == 4) ? maa[rr]   : 0.f;
            #pragma unroll
            for (int nf = 0; nf < 4; nf++) {
                int nc = n0g + wn * 32 + nf * 8 + (lane & 3) * 2;
                float v0 = acc[mf][nf][hf * 2 + 0];
                float v1 = acc[mf][nf][hf * 2 + 1];
                size_t off = (size_t)rr * Nn + nc;
                if (ACT == 1) { v0 = tanhf(v0); v1 = tanhf(v1); }
                else if (ACT == 2) { v0 = v0 / (1.f + expf(-v0)); v1 = v1 / (1.f + expf(-v1)); }
                else if (ACT == 3) { v0 = expf(-expf(e + v0)); v1 = expf(-expf(e + v1)); }
                else if (ACT == 4) {
                    float2 xv  = *(const float2*)&xb[off];
                    float2 xxv = *(const float2*)&xxb[off];
                    v0 = fmaf(xxv.x, mc + v0, xv.x);
                    v1 = fmaf(xxv.y, mc + v1, xv.y);
                }
                if (OUT == 0) {
                    *(float2*)&Yzf[off] = make_float2(v0, v1);
                } else {
                    __half2 h = __floats2half2_rn(v0, v1);
                    *(__half2*)&Yzh[off] = h;
                }
            }
        }
    }
}

// ---------------- K5: WKV6 scan, direct channel-major reads ------------------------
// 512 thr. Assembles (r,k,dec,v) float4 tile in smem; y staged and written coalesced.
__global__ void __launch_bounds__(512) scan_kernel(const float* __restrict__ u_in) {
    const int bh = blockIdx.x;
    const int h = bh % 12, b = bh / 12;
    const int t = threadIdx.x;
    const int jq = t & 7, i = t >> 3;          // i = 0..63
    __shared__ float4 buf[2][16][64];
    __shared__ __align__(16) float ytile[16][68];
    float S[8], uu[8];
    #pragma unroll
    for (int jj = 0; jj < 8; jj++) { S[jj] = 0.f; uu[jj] = u_in[h * 64 + jq + 8 * jj]; }

    const size_t cbase = ((size_t)b * 768 + h * 64) * 4096;
    const int a = t & 3, j = (t >> 2) & 63, nb = t >> 8;   // nb in {0,1}
    const float* ap = (a == 0) ? g_r : (a == 1) ? g_k : (a == 2) ? g_dec : g_v;
    const float* rowp = ap + cbase + (size_t)j * 4096;
    float* ydst = g_y + (size_t)b * 4096 * 768 + h * 64;

    float4 pre0 = *(const float4*)&rowp[nb * 4];
    float4 pre1 = *(const float4*)&rowp[(nb + 2) * 4];
    int cur = 0;
    for (int nt = 0; nt < 256; nt++) {
        {   // conflict-free: bank = (4j + a) % 32 covers all 32 banks across warp
            float* d0 = (float*)&buf[cur][nb * 4][j] + a;
            d0[0] = pre0.x; d0[256] = pre0.y; d0[512] = pre0.z; d0[768] = pre0.w;
            float* d1 = (float*)&buf[cur][(nb + 2) * 4][j] + a;
            d1[0] = pre1.x; d1[256] = pre1.y; d1[512] = pre1.z; d1[768] = pre1.w;
        }
        __syncthreads();
        if (nt + 1 < 256) {
            const float* np = rowp + (nt + 1) * 16;
            pre0 = *(const float4*)&np[nb * 4];
            pre1 = *(const float4*)&np[(nb + 2) * 4];
        }
        #pragma unroll
        for (int s = 0; s < 16; s++) {
            float vi = buf[cur][s][i].w;
            float p = 0.f;
            #pragma unroll
            for (int jj = 0; jj < 8; jj++) {
                float4 f = buf[cur][s][jq + 8 * jj];
                float kv = f.y * vi;
                float tmp = fmaf(uu[jj], kv, S[jj]);
                p = fmaf(f.x, tmp, p);
                S[jj] = fmaf(f.z, S[jj], kv);
            }
            p += __shfl_xor_sync(0xffffffffu, p, 1);
            p += __shfl_xor_sync(0xffffffffu, p, 2);
            p += __shfl_xor_sync(0xffffffffu, p, 4);
            if (jq == 0) ytile[s][i] = p;
        }
        __syncthreads();
        if (t < 256) {
            int tr = t >> 4, j4 = (t & 15) * 4;
            float4 o = *(float4*)&ytile[tr][j4];
            *(float4*)&ydst[(size_t)(nt * 16 + tr) * 768 + j4] = o;
        }
        cur ^= 1;
    }
}

// ---------------- K6: fused RMS + gate + transpose, fp16 channel-major out ---------
__global__ void __launch_bounds__(256) rmstgate_kernel(const float* __restrict__ lnw) {
    extern __shared__ float sy[];                 // [32][769]
    __shared__ float rmsv[32];
    const int t = threadIdx.x;
    const int tok0 = blockIdx.x * 32;
    const int b = tok0 >> 12, n0 = tok0 & 4095;
    const float* ybase = g_y + (size_t)tok0 * 768;

    #pragma unroll
    for (int it = 0; it < 24; it++) {
        int i = it * 256 + t;
        int tr = i / 192, c4 = i % 192;
        float4 v = *(const float4*)&ybase[(size_t)tr * 768 + c4 * 4];
        float* row = &sy[tr * 769];
        row[c4 * 4 + 0] = v.x; row[c4 * 4 + 1] = v.y;
        row[c4 * 4 + 2] = v.z; row[c4 * 4 + 3] = v.w;
    }
    __syncthreads();
    {
        int w = t >> 5, lane = t & 31;
        #pragma unroll
        for (int q = 0; q < 4; q++) {
            int tr = w * 4 + q;
            const float* row = &sy[tr * 769];
            float s = 0.f;
            #pragma unroll
            for (int jx = 0; jx < 24; jx++) { float v = row[lane + 32 * jx]; s += v * v; }
            #pragma unroll
            for (int off = 16; off; off >>= 1) s += __shfl_xor_sync(0xffffffffu, s, off);
            if (lane == 0) rmsv[tr] = rsqrtf(s * (1.f / 768.f) + 1e-6f);
        }
    }
    __syncthreads();
    #pragma unroll 4
    for (int it = 0; it < 96; it++) {
        int i = it * 256 + t;
        int c = i >> 5, tr = i & 31;
        float val = sy[tr * 769 + c];
        size_t go = ((size_t)(b * 768 + c)) * 4096 + n0 + tr;
        float g = __half2float(g_gateh[go]);
        g_y2h[go] = __float2half(val * rmsv[tr] * lnw[c] * g);
    }
}

// ---------------- launch ------------------------------------------------------------
extern "C" void kernel_launch(void* const* d_in, const int* in_sizes, int n_in,
                              void* d_out, int out_size) {
    const float* x        = (const float*)d_in[0];
    const float* maa_x    = (const float*)d_in[1];
    const float* maa_w    = (const float*)d_in[2];
    const float* maa_k    = (const float*)d_in[3];
    const float* maa_v    = (const float*)d_in[4];
    const float* maa_r    = (const float*)d_in[5];
    const float* maa_g    = (const float*)d_in[6];
    const float* maa_w1   = (const float*)d_in[7];
    const float* maa_w2   = (const float*)d_in[8];
    const float* tdecay   = (const float*)d_in[9];
    const float* td_w1    = (const float*)d_in[10];
    const float* td_w2    = (const float*)d_in[11];
    const float* faaaa    = (const float*)d_in[12];
    const float* key_w    = (const float*)d_in[13];
    const float* value_w  = (const float*)d_in[14];
    const float* recept_w = (const float*)d_in[15];
    const float* gate_w   = (const float*)d_in[16];
    const float* out_w    = (const float*)d_in[17];
    const float* ln_x_w   = (const float*)d_in[18];
    float* out = (float*)d_out;

    uint32_t *wh_t, *wh_w2, *wh_r, *wh_k, *wh_v, *wh_g, *wh_o, *wh_td1, *wh_td2;
    cudaGetSymbolAddress((void**)&wh_t,   g_wh_t);
    cudaGetSymbolAddress((void**)&wh_w2,  g_wh_w2);
    cudaGetSymbolAddress((void**)&wh_r,   g_wh_r);
    cudaGetSymbolAddress((void**)&wh_k,   g_wh_k);
    cudaGetSymbolAddress((void**)&wh_v,   g_wh_v);
    cudaGetSymbolAddress((void**)&wh_g,   g_wh_g);
    cudaGetSymbolAddress((void**)&wh_o,   g_wh_o);
    cudaGetSymbolAddress((void**)&wh_td1, g_wh_td1);
    cudaGetSymbolAddress((void**)&wh_td2, g_wh_td2);
    float *p_r, *p_k, *p_v, *p_dec;
    __half *p_xxxh, *p_th, *p_x5h, *p_gateh, *p_hh, *p_y2h;
    cudaGetSymbolAddress((void**)&p_xxxh, g_xxxh);
    cudaGetSymbolAddress((void**)&p_th,   g_th);
    cudaGetSymbolAddress((void**)&p_x5h,  g_x5h);
    cudaGetSymbolAddress((void**)&p_gateh,g_gateh);
    cudaGetSymbolAddress((void**)&p_hh,   g_hh);
    cudaGetSymbolAddress((void**)&p_y2h,  g_y2h);
    cudaGetSymbolAddress((void**)&p_r,    g_r);
    cudaGetSymbolAddress((void**)&p_k,    g_k);
    cudaGetSymbolAddress((void**)&p_v,    g_v);
    cudaGetSymbolAddress((void**)&p_dec,  g_dec);

    auto PREP = [&](const float* src, uint32_t* dst, int M, int Mp, int K, int tr, int nz) {
        size_t tot = (size_t)nz * (K >> 4) * (Mp >> 4) * 128;
        prep_wh<<<(unsigned)((tot + 255) / 256), 256>>>(src, dst, M, Mp, K, tr, nz);
    };
    PREP(maa_w1,   wh_t,   320, 384, 768, 0, 1);
    PREP(maa_w2,   wh_w2,  768, 768,  64, 1, 5);
    PREP(recept_w, wh_r,   384, 384, 384, 0, 2);
    PREP(key_w,    wh_k,   384, 384, 384, 0, 2);
    PREP(value_w,  wh_v,   384, 384, 384, 0, 2);
    PREP(gate_w,   wh_g,   384, 384, 384, 0, 2);
    PREP(out_w,    wh_o,   384, 384, 384, 0, 2);
    PREP(td_w1,    wh_td1,  64, 128, 768, 0, 1);
    PREP(td_w2,    wh_td2, 768, 768,  64, 0, 1);

    shift_kernel<<<(BCN + 255) / 256, 256>>>(x, maa_x);

    #define NUL5 nullptr, nullptr, nullptr, nullptr, nullptr
    long long sC    = (long long)Cc * Nn;
    long long s384  = (long long)384 * Nn;
    long long s128  = (long long)128 * Nn;

    // t = tanh(maa_w1 @ xxx): Mp=384, K=768, z=B  (fp16 in/out)
    gemm_h<1,1><<<dim3(32, 3, 8), 256>>>(wh_t, p_xxxh, p_th, 384, 768, 1,
                                         sC, s384, nullptr, nullptr, NUL5);

    // x5h = x + xx*(maa + W2 @ t): z=b*5+s (40)  (fp16 in/out; x/xx fp32 in epilogue)
    gemm_h<4,1><<<dim3(32, 6, 40), 256>>>(wh_w2, p_th, p_x5h, 768, 64, 5,
                                          0, sC, nullptr, x,
                                          maa_w, maa_k, maa_v, maa_r, maa_g);

    // grouped convs -> contiguous fp32 channel-major (scan reads these directly)
    gemm_h<0,0><<<dim3(32, 3, 16), 256>>>(wh_r, p_x5h + (size_t)3*BCN, p_r, 384, 384, 2,
                                          s384, s384, nullptr, nullptr, NUL5);
    gemm_h<0,0><<<dim3(32, 3, 16), 256>>>(wh_k, p_x5h + (size_t)1*BCN, p_k, 384, 384, 2,
                                          s384, s384, nullptr, nullptr, NUL5);
    gemm_h<0,0><<<dim3(32, 3, 16), 256>>>(wh_v, p_x5h + (size_t)2*BCN, p_v, 384, 384, 2,
                                          s384, s384, nullptr, nullptr, NUL5);
    gemm_h<2,1><<<dim3(32, 3, 16), 256>>>(wh_g, p_x5h + (size_t)4*BCN, p_gateh, 384, 384, 2,
                                          s384, s384, nullptr, nullptr, NUL5);

    // decay MLP: h = tanh(td_w1 @ xw) (fp16); dec = exp(-exp(td + td_w2 @ h)) (fp32)
    gemm_h<1,1><<<dim3(32, 1, 8), 256>>>(wh_td1, p_x5h, p_hh, 128, 768, 1,
                                         sC, s128, nullptr, nullptr, NUL5);
    gemm_h<3,0><<<dim3(32, 6, 8), 256>>>(wh_td2, p_hh, p_dec, 768, 64, 1,
                                         s128, sC, tdecay, nullptr, NUL5);

    // scan (reads g_r/g_k/g_dec/g_v directly)
    scan_kernel<<<96, 512>>>(faaaa);

    // fused rms + gate + transpose -> y2h
    cudaFuncSetAttribute(rmstgate_kernel, cudaFuncAttributeMaxDynamicSharedMemorySize,
                         32 * 769 * 4);
    rmstgate_kernel<<<TOK / 32, 256, 32 * 769 * 4>>>(ln_x_w);

    // final grouped conv -> out (fp32 channel-major)
    gemm_h<0,0><<<dim3(32, 3, 16), 256>>>(wh_o, p_y2h, out, 384, 384, 2,
                                          s384, s384, nullptr, nullptr, NUL5);
}

// round 12
// speedup vs baseline: 2.0363x; 1.1331x over previous
#include <cuda_runtime.h>
#include <cuda_fp16.h>
#include <cstdint>
#include <cstddef>

#define Bb 8
#define Cc 768
#define Nn 4096
#define TOK (Bb*Nn)
#define BCN (Bb*Cc*Nn)   // 25165824

typedef unsigned long long ull;

// ---------------- scratch (static device globals) ---------------------------------
__device__ __align__(16) float  g_xx  [BCN];              // channel-major (B,C,N)
__device__ __align__(16) __half g_xxxh[BCN];              // fp16 (mma operand only)
__device__ __align__(16) __half g_th  [Bb*384*Nn];        // t, fp16
__device__ __align__(16) __half g_x5h [5u*(size_t)BCN];   // s: 0=xw 1=xk 2=xv 3=xr 4=xg
__device__ __align__(16) __half g_gateh[BCN];
__device__ __align__(16) __half g_hh  [(size_t)Bb*128*Nn];// decay hidden fp16 (padded)
__device__ __align__(16) float  g_r   [BCN];              // conv outputs fp32 (b,c,n)
__device__ __align__(16) float  g_k   [BCN];
__device__ __align__(16) float  g_v   [BCN];
__device__ __align__(16) float  g_dec [BCN];
__device__ __align__(16) float  g_y   [BCN];              // scan out (b,n,c)
__device__ __align__(16) __half g_y2h [BCN];              // normalized+gated (b,c,n)
// fp16 fragment-packed weights: [z][kt][mfr][lane][4] uint32 (half2)
__device__ __align__(16) uint32_t g_wh_t  [48*24*128];
__device__ __align__(16) uint32_t g_wh_w2 [5*4*48*128];
__device__ __align__(16) uint32_t g_wh_r  [2*24*24*128];
__device__ __align__(16) uint32_t g_wh_k  [2*24*24*128];
__device__ __align__(16) uint32_t g_wh_v  [2*24*24*128];
__device__ __align__(16) uint32_t g_wh_g  [2*24*24*128];
__device__ __align__(16) uint32_t g_wh_o  [2*24*24*128];
__device__ __align__(16) uint32_t g_wh_td1[48*8*128];
__device__ __align__(16) uint32_t g_wh_td2[4*48*128];

// ---------------- asm helpers ------------------------------------------------------
__device__ __forceinline__ uint32_t s2u(const void* p) {
    uint32_t a;
    asm("{ .reg .u64 t; cvta.to.shared.u64 t, %1; cvt.u32.u64 %0, t; }" : "=r"(a) : "l"(p));
    return a;
}
__device__ __forceinline__ void mma16(float* d, const uint4& a, uint32_t b0, uint32_t b1) {
    asm volatile("mma.sync.aligned.m16n8k16.row.col.f32.f16.f16.f32 "
        "{%0,%1,%2,%3}, {%4,%5,%6,%7}, {%8,%9}, {%0,%1,%2,%3};"
        : "+f"(d[0]), "+f"(d[1]), "+f"(d[2]), "+f"(d[3])
        : "r"(a.x), "r"(a.y), "r"(a.z), "r"(a.w), "r"(b0), "r"(b1));
}
__device__ __forceinline__ void ldmB(uint32_t& b0, uint32_t& b1, uint32_t addr) {
    asm volatile("ldmatrix.sync.aligned.m8n8.x2.trans.shared.b16 {%0,%1}, [%2];"
        : "=r"(b0), "=r"(b1) : "r"(addr));
}
// packed f32x2 ops (sm_103a)
__device__ __forceinline__ ull pk2(float lo, float hi) {
    ull d; asm("mov.b64 %0, {%1, %2};" : "=l"(d) : "f"(lo), "f"(hi)); return d;
}
__device__ __forceinline__ void upk2(float& lo, float& hi, ull v) {
    asm("mov.b64 {%0, %1}, %2;" : "=f"(lo), "=f"(hi) : "l"(v));
}
__device__ __forceinline__ ull mul2(ull a, ull b) {
    ull d; asm("mul.rn.f32x2 %0, %1, %2;" : "=l"(d) : "l"(a), "l"(b)); return d;
}
__device__ __forceinline__ ull fma2(ull a, ull b, ull c) {
    ull d; asm("fma.rn.f32x2 %0, %1, %2, %3;" : "=l"(d) : "l"(a), "l"(b), "l"(c)); return d;
}

// ---------------- weight prep: fragment-packed fp16 --------------------------------
__global__ void prep_wh(const float* __restrict__ src, uint32_t* __restrict__ dst,
                        int M, int Mp, int K, int trans, int nz) {
    size_t idx = (size_t)blockIdx.x * 256 + threadIdx.x;
    int KT = K >> 4, MFR = Mp >> 4;
    size_t per_z = (size_t)KT * MFR * 128;
    if (idx >= per_z * nz) return;
    int z = (int)(idx / per_z);
    size_t rem = idx - (size_t)z * per_z;
    int kt  = (int)(rem / (MFR * 128));
    int r2  = (int)(rem % (MFR * 128));
    int mfr = r2 >> 7;
    int li  = r2 & 127;
    int lane = li >> 2, r = li & 3;
    int m = mfr * 16 + (lane >> 2) + ((r & 1) << 3);
    int k = kt * 16 + (lane & 3) * 2 + ((r >> 1) << 3);
    float f0 = 0.f, f1 = 0.f;
    if (m < M) {
        const float* sz = src + (size_t)z * M * K;
        if (trans) { f0 = sz[(size_t)k * M + m]; f1 = sz[(size_t)(k + 1) * M + m]; }
        else       { f0 = sz[(size_t)m * K + k]; f1 = sz[(size_t)m * K + k + 1]; }
    }
    __half2 h = __floats2half2_rn(f0, f1);
    dst[idx] = *(uint32_t*)&h;
}

// ---------------- K1: q_shift + xx(fp32) + xxx(fp16) -------------------------------
__global__ void shift_kernel(const float* __restrict__ x, const float* __restrict__ maa_x) {
    size_t idx = (size_t)blockIdx.x * 256 + threadIdx.x;
    if (idx >= (size_t)BCN) return;
    int n = (int)(idx & (Nn - 1));
    int c = (int)((idx >> 12) % Cc);
    int w = n & 63, hh = n >> 6;
    float xv = x[idx], s;
    int mode = c / 192;
    if (mode == 0)      s = (w  > 0 ) ? x[idx - 1 ] : 0.f;
    else if (mode == 1) s = (w  < 63) ? x[idx + 1 ] : 0.f;
    else if (mode == 2) s = (hh > 0 ) ? x[idx - 64] : 0.f;
    else                s = (hh < 63) ? x[idx + 64] : 0.f;
    float d = s - xv;
    g_xx[idx]   = d;
    g_xxxh[idx] = __float2half(fmaf(d, maa_x[c], xv));
}

// ---------------- fp16 tensor-core GEMM --------------------------------------------
template<int ACT, int OUT>
__global__ void __launch_bounds__(256) gemm_h(
    const uint32_t* __restrict__ Wp, const __half* __restrict__ X,
    void* __restrict__ Yv, int Mp, int K, int wmod,
    long long sXz, long long sYz,
    const float* __restrict__ extra, const float* __restrict__ xin,
    const float* __restrict__ q0, const float* __restrict__ q1,
    const float* __restrict__ q2, const float* __restrict__ q3,
    const float* __restrict__ q4)
{
    const int z   = blockIdx.z;
    const int m0g = blockIdx.y * 128;
    const int n0g = blockIdx.x * 128;
    const int KT = K >> 4, MFR = Mp >> 4;

    const uint32_t* Wz;
    const __half* Xz;
    float* Yzf = nullptr; __half* Yzh = nullptr;
    const float* maa = nullptr; const float* xb = nullptr; const float* xxb = nullptr;
    if (ACT == 4) {
        int s = z % 5, b = z / 5;
        Wz = Wp + (size_t)s * KT * MFR * 128;
        Xz = X + (size_t)b * 384 * Nn + (size_t)s * 64 * Nn;
        Yzh = (__half*)Yv + (size_t)(s * 8 + b) * sYz;
        maa = (s==0)?q0:(s==1)?q1:(s==2)?q2:(s==3)?q3:q4;
        xb  = xin + (size_t)b * Cc * Nn;
        xxb = g_xx + (size_t)b * Cc * Nn;
    } else {
        Wz = Wp + (size_t)(z % wmod) * KT * MFR * 128;
        Xz = X + (size_t)z * sXz;
        if (OUT == 0) Yzf = (float*)Yv + (size_t)z * sYz;
        else          Yzh = (__half*)Yv + (size_t)z * sYz;
    }

    __shared__ __align__(16) __half Bs[2][16][136];

    const int t = threadIdx.x;
    const int lane = t & 31, wid = t >> 5;
    const int wm = wid >> 2, wn = wid & 3;

    float acc[4][4][4];
    #pragma unroll
    for (int i = 0; i < 4; i++)
        #pragma unroll
        for (int jx = 0; jx < 4; jx++)
            #pragma unroll
            for (int q = 0; q < 4; q++) acc[i][jx][q] = 0.f;

    uint4 aR[2][4];
    uint4 bRh;

    #pragma unroll
    for (int mf = 0; mf < 4; mf++) {
        int mfr = (m0g >> 4) + wm * 4 + mf;
        aR[0][mf] = *(const uint4*)&Wz[(((size_t)0 * MFR + mfr) * 32 + lane) * 4];
    }
    {
        int k = t >> 4, c8 = (t & 15) * 8;
        bRh = *(const uint4*)&Xz[(size_t)k * Nn + n0g + c8];
    }

    for (int kt = 0; kt < KT; kt++) {
        int buf = kt & 1;
        {
            int k = t >> 4, c8 = (t & 15) * 8;
            *(uint4*)&Bs[buf][k][c8] = bRh;
        }
        __syncthreads();
        if (kt + 1 < KT) {
            #pragma unroll
            for (int mf = 0; mf < 4; mf++) {
                int mfr = (m0g >> 4) + wm * 4 + mf;
                aR[buf ^ 1][mf] =
                    *(const uint4*)&Wz[(((size_t)(kt + 1) * MFR + mfr) * 32 + lane) * 4];
            }
            int k = t >> 4, c8 = (t & 15) * 8;
            bRh = *(const uint4*)&Xz[(size_t)((kt + 1) * 16 + k) * Nn + n0g + c8];
        }
        uint32_t base = s2u(&Bs[buf][lane & 15][wn * 32]);
        uint32_t bf[4][2];
        #pragma unroll
        for (int nf = 0; nf < 4; nf++) ldmB(bf[nf][0], bf[nf][1], base + nf * 16);
        #pragma unroll
        for (int mf = 0; mf < 4; mf++)
            #pragma unroll
            for (int nf = 0; nf < 4; nf++)
                mma16(acc[mf][nf], aR[buf][mf], bf[nf][0], bf[nf][1]);
        __syncthreads();
    }

    #pragma unroll
    for (int mf = 0; mf < 4; mf++) {
        int rr0 = m0g + wm * 64 + mf * 16 + (lane >> 2);
        #pragma unroll
        for (int hf = 0; hf < 2; hf++) {
            int rr = rr0 + hf * 8;
            float e  = (ACT == 3) ? extra[rr] : 0.f;
            float mc = (ACT == 4) ? maa[rr]   : 0.f;
            #pragma unroll
            for (int nf = 0; nf < 4; nf++) {
                int nc = n0g + wn * 32 + nf * 8 + (lane & 3) * 2;
                float v0 = acc[mf][nf][hf * 2 + 0];
                float v1 = acc[mf][nf][hf * 2 + 1];
                size_t off = (size_t)rr * Nn + nc;
                if (ACT == 1) { v0 = tanhf(v0); v1 = tanhf(v1); }
                else if (ACT == 2) { v0 = v0 / (1.f + expf(-v0)); v1 = v1 / (1.f + expf(-v1)); }
                else if (ACT == 3) { v0 = expf(-expf(e + v0)); v1 = expf(-expf(e + v1)); }
                else if (ACT == 4) {
                    float2 xv  = *(const float2*)&xb[off];
                    float2 xxv = *(const float2*)&xxb[off];
                    v0 = fmaf(xxv.x, mc + v0, xv.x);
                    v1 = fmaf(xxv.y, mc + v1, xv.y);
                }
                if (OUT == 0) {
                    *(float2*)&Yzf[off] = make_float2(v0, v1);
                } else {
                    __half2 h = __floats2half2_rn(v0, v1);
                    *(__half2*)&Yzh[off] = h;
                }
            }
        }
    }
}

// ---------------- K5: WKV6 scan, packed f32x2 --------------------------------------
// 512 thr. Thread (i = t>>3, jq = t&7) owns j-pairs {2jq+16p, 2jq+16p+1}, p=0..3.
// Separate smem comp arrays; k/d/r pair loads are 8-distinct LDS.64 broadcasts.
__global__ void __launch_bounds__(512) scan_kernel(const float* __restrict__ u_in) {
    const int bh = blockIdx.x;
    const int h = bh % 12, b = bh / 12;
    const int t = threadIdx.x;
    const int jq = t & 7, i = t >> 3;          // i = 0..63
    __shared__ __align__(16) float sm[4][2][16][68];   // comp r,k,d,v
    __shared__ __align__(16) float ytile[16][68];

    ull S2[4], u2[4], p2;
    #pragma unroll
    for (int p = 0; p < 4; p++) {
        S2[p] = 0ull;
        int j = 2 * jq + 16 * p;
        u2[p] = pk2(u_in[h * 64 + j], u_in[h * 64 + j + 1]);
    }

    const size_t cbase = ((size_t)b * 768 + h * 64) * 4096;
    const int csel = t >> 7, jldr = t & 63, nb = (t >> 6) & 1;
    const float* ap = (csel == 0) ? g_r : (csel == 1) ? g_k : (csel == 2) ? g_dec : g_v;
    const float* rowp = ap + cbase + (size_t)jldr * 4096;
    float* ydst = g_y + (size_t)b * 4096 * 768 + h * 64;

    float4 pre0 = *(const float4*)&rowp[nb * 4];
    float4 pre1 = *(const float4*)&rowp[(nb + 2) * 4];
    int cur = 0;
    for (int nt = 0; nt < 256; nt++) {
        {
            float* c0 = &sm[csel][cur][nb * 4][jldr];
            c0[0] = pre0.x; c0[68] = pre0.y; c0[136] = pre0.z; c0[204] = pre0.w;
            float* c1 = &sm[csel][cur][(nb + 2) * 4][jldr];
            c1[0] = pre1.x; c1[68] = pre1.y; c1[136] = pre1.z; c1[204] = pre1.w;
        }
        __syncthreads();
        if (nt + 1 < 256) {
            const float* np = rowp + (nt + 1) * 16;
            pre0 = *(const float4*)&np[nb * 4];
            pre1 = *(const float4*)&np[(nb + 2) * 4];
        }
        #pragma unroll
        for (int s = 0; s < 16; s++) {
            float v = sm[3][cur][s][i];
            ull v2 = pk2(v, v);
            p2 = 0ull;
            #pragma unroll
            for (int p = 0; p < 4; p++) {
                int j = 2 * jq + 16 * p;
                ull kk = *(const ull*)&sm[1][cur][s][j];
                ull dd = *(const ull*)&sm[2][cur][s][j];
                ull rr = *(const ull*)&sm[0][cur][s][j];
                ull kv = mul2(kk, v2);
                ull tmp = fma2(u2[p], kv, S2[p]);
                p2 = fma2(rr, tmp, p2);
                S2[p] = fma2(dd, S2[p], kv);
            }
            float plo, phi; upk2(plo, phi, p2);
            float pp = plo + phi;
            pp += __shfl_xor_sync(0xffffffffu, pp, 1);
            pp += __shfl_xor_sync(0xffffffffu, pp, 2);
            pp += __shfl_xor_sync(0xffffffffu, pp, 4);
            if (jq == 0) ytile[s][i] = pp;
        }
        __syncthreads();
        if (t < 256) {
            int tr = t >> 4, j4 = (t & 15) * 4;
            float4 o = *(float4*)&ytile[tr][j4];
            *(float4*)&ydst[(size_t)(nt * 16 + tr) * 768 + j4] = o;
        }
        cur ^= 1;
    }
}

// ---------------- K6: fused RMS + gate + transpose, fp16 channel-major out ---------
__global__ void __launch_bounds__(256) rmstgate_kernel(const float* __restrict__ lnw) {
    extern __shared__ float sy[];                 // [32][769]
    __shared__ float rmsv[32];
    const int t = threadIdx.x;
    const int tok0 = blockIdx.x * 32;
    const int b = tok0 >> 12, n0 = tok0 & 4095;
    const float* ybase = g_y + (size_t)tok0 * 768;

    #pragma unroll
    for (int it = 0; it < 24; it++) {
        int i = it * 256 + t;
        int tr = i / 192, c4 = i % 192;
        float4 v = *(const float4*)&ybase[(size_t)tr * 768 + c4 * 4];
        float* row = &sy[tr * 769];
        row[c4 * 4 + 0] = v.x; row[c4 * 4 + 1] = v.y;
        row[c4 * 4 + 2] = v.z; row[c4 * 4 + 3] = v.w;
    }
    __syncthreads();
    {
        int w = t >> 5, lane = t & 31;
        #pragma unroll
        for (int q = 0; q < 4; q++) {
            int tr = w * 4 + q;
            const float* row = &sy[tr * 769];
            float s = 0.f;
            #pragma unroll
            for (int jx = 0; jx < 24; jx++) { float v = row[lane + 32 * jx]; s += v * v; }
            #pragma unroll
            for (int off = 16; off; off >>= 1) s += __shfl_xor_sync(0xffffffffu, s, off);
            if (lane == 0) rmsv[tr] = rsqrtf(s * (1.f / 768.f) + 1e-6f);
        }
    }
    __syncthreads();
    #pragma unroll 4
    for (int it = 0; it < 96; it++) {
        int i = it * 256 + t;
        int c = i >> 5, tr = i & 31;
        float val = sy[tr * 769 + c];
        size_t go = ((size_t)(b * 768 + c)) * 4096 + n0 + tr;
        float g = __half2float(g_gateh[go]);
        g_y2h[go] = __float2half(val * rmsv[tr] * lnw[c] * g);
    }
}

// ---------------- launch ------------------------------------------------------------
extern "C" void kernel_launch(void* const* d_in, const int* in_sizes, int n_in,
                              void* d_out, int out_size) {
    const float* x        = (const float*)d_in[0];
    const float* maa_x    = (const float*)d_in[1];
    const float* maa_w    = (const float*)d_in[2];
    const float* maa_k    = (const float*)d_in[3];
    const float* maa_v    = (const float*)d_in[4];
    const float* maa_r    = (const float*)d_in[5];
    const float* maa_g    = (const float*)d_in[6];
    const float* maa_w1   = (const float*)d_in[7];
    const float* maa_w2   = (const float*)d_in[8];
    const float* tdecay   = (const float*)d_in[9];
    const float* td_w1    = (const float*)d_in[10];
    const float* td_w2    = (const float*)d_in[11];
    const float* faaaa    = (const float*)d_in[12];
    const float* key_w    = (const float*)d_in[13];
    const float* value_w  = (const float*)d_in[14];
    const float* recept_w = (const float*)d_in[15];
    const float* gate_w   = (const float*)d_in[16];
    const float* out_w    = (const float*)d_in[17];
    const float* ln_x_w   = (const float*)d_in[18];
    float* out = (float*)d_out;

    uint32_t *wh_t, *wh_w2, *wh_r, *wh_k, *wh_v, *wh_g, *wh_o, *wh_td1, *wh_td2;
    cudaGetSymbolAddress((void**)&wh_t,   g_wh_t);
    cudaGetSymbolAddress((void**)&wh_w2,  g_wh_w2);
    cudaGetSymbolAddress((void**)&wh_r,   g_wh_r);
    cudaGetSymbolAddress((void**)&wh_k,   g_wh_k);
    cudaGetSymbolAddress((void**)&wh_v,   g_wh_v);
    cudaGetSymbolAddress((void**)&wh_g,   g_wh_g);
    cudaGetSymbolAddress((void**)&wh_o,   g_wh_o);
    cudaGetSymbolAddress((void**)&wh_td1, g_wh_td1);
    cudaGetSymbolAddress((void**)&wh_td2, g_wh_td2);
    float *p_r, *p_k, *p_v, *p_dec;
    __half *p_xxxh, *p_th, *p_x5h, *p_gateh, *p_hh, *p_y2h;
    cudaGetSymbolAddress((void**)&p_xxxh, g_xxxh);
    cudaGetSymbolAddress((void**)&p_th,   g_th);
    cudaGetSymbolAddress((void**)&p_x5h,  g_x5h);
    cudaGetSymbolAddress((void**)&p_gateh,g_gateh);
    cudaGetSymbolAddress((void**)&p_hh,   g_hh);
    cudaGetSymbolAddress((void**)&p_y2h,  g_y2h);
    cudaGetSymbolAddress((void**)&p_r,    g_r);
    cudaGetSymbolAddress((void**)&p_k,    g_k);
    cudaGetSymbolAddress((void**)&p_v,    g_v);
    cudaGetSymbolAddress((void**)&p_dec,  g_dec);

    auto PREP = [&](const float* src, uint32_t* dst, int M, int Mp, int K, int tr, int nz) {
        size_t tot = (size_t)nz * (K >> 4) * (Mp >> 4) * 128;
        prep_wh<<<(unsigned)((tot + 255) / 256), 256>>>(src, dst, M, Mp, K, tr, nz);
    };
    PREP(maa_w1,   wh_t,   320, 384, 768, 0, 1);
    PREP(maa_w2,   wh_w2,  768, 768,  64, 1, 5);
    PREP(recept_w, wh_r,   384, 384, 384, 0, 2);
    PREP(key_w,    wh_k,   384, 384, 384, 0, 2);
    PREP(value_w,  wh_v,   384, 384, 384, 0, 2);
    PREP(gate_w,   wh_g,   384, 384, 384, 0, 2);
    PREP(out_w,    wh_o,   384, 384, 384, 0, 2);
    PREP(td_w1,    wh_td1,  64, 128, 768, 0, 1);
    PREP(td_w2,    wh_td2, 768, 768,  64, 0, 1);

    shift_kernel<<<(BCN + 255) / 256, 256>>>(x, maa_x);

    #define NUL5 nullptr, nullptr, nullptr, nullptr, nullptr
    long long sC    = (long long)Cc * Nn;
    long long s384  = (long long)384 * Nn;
    long long s128  = (long long)128 * Nn;

    gemm_h<1,1><<<dim3(32, 3, 8), 256>>>(wh_t, p_xxxh, p_th, 384, 768, 1,
                                         sC, s384, nullptr, nullptr, NUL5);

    gemm_h<4,1><<<dim3(32, 6, 40), 256>>>(wh_w2, p_th, p_x5h, 768, 64, 5,
                                          0, sC, nullptr, x,
                                          maa_w, maa_k, maa_v, maa_r, maa_g);

    gemm_h<0,0><<<dim3(32, 3, 16), 256>>>(wh_r, p_x5h + (size_t)3*BCN, p_r, 384, 384, 2,
                                          s384, s384, nullptr, nullptr, NUL5);
    gemm_h<0,0><<<dim3(32, 3, 16), 256>>>(wh_k, p_x5h + (size_t)1*BCN, p_k, 384, 384, 2,
                                          s384, s384, nullptr, nullptr, NUL5);
    gemm_h<0,0><<<dim3(32, 3, 16), 256>>>(wh_v, p_x5h + (size_t)2*BCN, p_v, 384, 384, 2,
                                          s384, s384, nullptr, nullptr, NUL5);
    gemm_h<2,1><<<dim3(32, 3, 16), 256>>>(wh_g, p_x5h + (size_t)4*BCN, p_gateh, 384, 384, 2,
                                          s384, s384, nullptr, nullptr, NUL5);

    gemm_h<1,1><<<dim3(32, 1, 8), 256>>>(wh_td1, p_x5h, p_hh, 128, 768, 1,
                                         sC, s128, nullptr, nullptr, NUL5);
    gemm_h<3,0><<<dim3(32, 6, 8), 256>>>(wh_td2, p_hh, p_dec, 768, 64, 1,
                                         s128, sC, tdecay, nullptr, NUL5);

    scan_kernel<<<96, 512>>>(faaaa);

    cudaFuncSetAttribute(rmstgate_kernel, cudaFuncAttributeMaxDynamicSharedMemorySize,
                         32 * 769 * 4);
    rmstgate_kernel<<<TOK / 32, 256, 32 * 769 * 4>>>(ln_x_w);

    gemm_h<0,0><<<dim3(32, 3, 16), 256>>>(wh_o, p_y2h, out, 384, 384, 2,
                                          s384, s384, nullptr, nullptr, NUL5);
}